// round 13
// baseline (speedup 1.0000x reference)
#include <cuda_runtime.h>
#include <cuda_fp16.h>
#include <cstdint>
#include <cstddef>

#define NN 100000
#define NE 1600000
#define NBLK 391   // ceil(NN/256)

// segment geometry
#define M0 30000
#define M1 50000
#define M2 20000
#define K0 256
#define K1 512
#define K2 128
#define IN0_OFF 0
#define IN1_OFF (M0 * K0)                    // 7,680,000
#define IN2_OFF (M0 * K0 + M1 * K1)          // 33,280,000
#define W0_OFF 0
#define W1_OFF (128 * K0)                    // 32768
#define W2_OFF (128 * K0 + 128 * K1)         // 98304
#define WF0_OFF 0
#define WF1_OFF (K0 * 128)
#define WF2_OFF ((K0 + K1) * 128)

// ---------------- scratch (static __device__, no allocations) ----------------
__device__ __align__(128) __half g_in_h[M0 * K0 + M1 * K1 + M2 * K2];  // fp16 inputs
__device__ __align__(128) __half g_w_h[128 * (K0 + K1 + K2)];          // fp16 lin weights, n-major [o][i]
__device__ __align__(128) __half g_x_h[NN * 128];        // fp16 projected features
__device__ __align__(128) __half g_xt_h[6 * NN * 64];    // per-relation transformed, layer 1 (fp16)
__device__ __align__(128) float  g_y[NN * 64];           // layer-1 output
__device__ __align__(128) float  g_xt2[6 * NN * 16];     // per-relation transformed, layer 2
__device__ __align__(128) float  g_z[NN * 16];           // layer-2 output
__device__ __align__(128) float  g_inv[6 * NN];          // 1/max(cnt,1)
__device__ int   g_cnt[6 * NN];
__device__ int   g_deg[NN];
__device__ int   g_pos[NN];
__device__ int   g_bsum[NBLK];
__device__ int   g_rowptr[NN + 1];
__device__ int   g_eidx[NE];                             // packed src | (et<<17)
__device__ __align__(128) __half g_W1ct_h[384 * 128];    // fp16 n-major: [(r*64+o)][k]
__device__ __align__(128) float  g_Wf[(K0 + K1 + K2) * 128];  // fused root weights [i][0..63], pad 64..127=0
__device__ __align__(128) float  g_bf[3 * 64];           // fused root bias per segment
__device__ __align__(128) float  g_W2c[64 * 128];        // [k][r*16+o], r=0..5 rels, 6=root, 7=pad

// ---------------- convert inputs to fp16 (vectorized float4 -> 2x half2) ----------------
__global__ __launch_bounds__(256) void convIn_k(const float* __restrict__ x0,
                                                const float* __restrict__ x1,
                                                const float* __restrict__ x2) {
    const int TOT4 = (M0 * K0 + M1 * K1 + M2 * K2) / 4;   // 8,960,000
    int idx = blockIdx.x * blockDim.x + threadIdx.x;
    if (idx >= TOT4) return;
    int e = idx * 4;
    const float* src;
    int off;
    if (e < IN1_OFF)      { src = x0; off = e; }
    else if (e < IN2_OFF) { src = x1; off = e - IN1_OFF; }
    else                  { src = x2; off = e - IN2_OFF; }
    float4 v = *reinterpret_cast<const float4*>(src + off);
    __half2 h0 = __floats2half2_rn(v.x, v.y);
    __half2 h1 = __floats2half2_rn(v.z, v.w);
    __half2* dst = reinterpret_cast<__half2*>(g_in_h + e);
    dst[0] = h0; dst[1] = h1;
}

// ---------------- weight prep: fp16 lin weights, fused root weights + bias ----------------
__global__ __launch_bounds__(256) void prepW_k(const float* __restrict__ lw0,
                                               const float* __restrict__ lw1,
                                               const float* __restrict__ lw2,
                                               const float* __restrict__ lb0,
                                               const float* __restrict__ lb1,
                                               const float* __restrict__ lb2,
                                               const float* __restrict__ root1,
                                               const float* __restrict__ bias1) {
    const int NW = 128 * (K0 + K1 + K2);        // 114688 fp16 weight copies
    const int NF = (K0 + K1 + K2) * 64;         // 57344 fused-weight outputs
    int idx = blockIdx.x * blockDim.x + threadIdx.x;
    if (idx < NW) {
        // straight fp16 copy: g_w_h is n-major [o][i] == original lw layout
        float v;
        if (idx < W1_OFF)       v = lw0[idx];
        else if (idx < W2_OFF)  v = lw1[idx - W1_OFF];
        else                    v = lw2[idx - W2_OFF];
        g_w_h[idx] = __float2half(v);
    } else if (idx < NW + NF) {
        int j = idx - NW;
        int i = j >> 6, o = j & 63;             // i = global in-dim index 0..895
        const float* lw; int K, ioff, wfoff;
        if (i < K0)            { lw = lw0; K = K0; ioff = i;            wfoff = WF0_OFF; }
        else if (i < K0 + K1)  { lw = lw1; K = K1; ioff = i - K0;       wfoff = WF1_OFF; }
        else                   { lw = lw2; K = K2; ioff = i - K0 - K1;  wfoff = WF2_OFF; }
        float s = 0.f;
        #pragma unroll 8
        for (int k = 0; k < 128; k++)
            s = fmaf(lw[k * K + ioff], root1[k * 64 + o], s);
        int row = (wfoff >> 7) + ioff;          // local row within g_Wf
        g_Wf[(size_t)row * 128 + o] = s;
        g_Wf[(size_t)row * 128 + 64 + o] = 0.f;
    } else if (idx < NW + NF + 192) {
        int j = idx - NW - NF;
        int s = j >> 6, o = j & 63;
        const float* lb = (s == 0) ? lb0 : (s == 1) ? lb1 : lb2;
        float acc = bias1[o];
        #pragma unroll 8
        for (int k = 0; k < 128; k++)
            acc = fmaf(lb[k], root1[k * 64 + o], acc);
        g_bf[s * 64 + o] = acc;
    }
}

// merged basis-composition for both layers (layer-1 rel fp16, layer-2 fp32)
__global__ __launch_bounds__(256) void compWc_k(const float* __restrict__ comp1,
                                                const float* __restrict__ bases1,
                                                const float* __restrict__ comp2,
                                                const float* __restrict__ bases2,
                                                const float* __restrict__ root2) {
    int idx = blockIdx.x * blockDim.x + threadIdx.x;
    if (idx < 128 * 384) {
        int i = idx / 384, c = idx - i * 384;    // i = k, c = r*64+o
        int r = c >> 6, o = c & 63;
        float s = 0.f;
        #pragma unroll 6
        for (int b = 0; b < 30; b++)
            s = fmaf(comp1[r * 30 + b], bases1[b * 8192 + i * 64 + o], s);
        g_W1ct_h[(size_t)c * 128 + i] = __float2half(s);   // n-major
    } else if (idx < 128 * 384 + 64 * 128) {
        int j = idx - 128 * 384;
        int k = j >> 7, c = j & 127;
        int r = c >> 4, o = c & 15;
        float s = 0.f;
        if (r < 6) {
            #pragma unroll 6
            for (int b = 0; b < 30; b++)
                s = fmaf(comp2[r * 30 + b], bases2[b * 1024 + k * 16 + o], s);
        } else if (r == 6) {
            s = root2[k * 16 + o];
        }
        g_W2c[j] = s;
    }
}

__global__ __launch_bounds__(256) void zero_k() {
    int i = blockIdx.x * blockDim.x + threadIdx.x;
    if (i < 6 * NN) g_cnt[i] = 0;
    if (i < NN) g_pos[i] = 0;
}

__global__ __launch_bounds__(256) void count_k(const int* __restrict__ ei,
                                               const int* __restrict__ et) {
    int e = blockIdx.x * blockDim.x + threadIdx.x;
    if (e < NE) {
        int dst = ei[NE + e];
        int t = et[e];
        atomicAdd(&g_cnt[t * NN + dst], 1);
    }
}

__global__ __launch_bounds__(256) void prep_k() {
    int i = blockIdx.x * blockDim.x + threadIdx.x;
    if (i < 6 * NN) {
        int c = g_cnt[i];
        g_inv[i] = 1.0f / (float)(c > 1 ? c : 1);
    }
    if (i < NN) {
        int d = 0;
        #pragma unroll
        for (int r = 0; r < 6; r++) d += g_cnt[r * NN + i];
        g_deg[i] = d;
    }
}

// ---- 3-phase parallel scan of g_deg -> g_rowptr ----
__global__ __launch_bounds__(256) void scanA_k() {
    __shared__ int s[256];
    int t = threadIdx.x;
    int idx = blockIdx.x * 256 + t;
    int v = (idx < NN) ? g_deg[idx] : 0;
    s[t] = v;
    __syncthreads();
    for (int off = 128; off > 0; off >>= 1) {
        if (t < off) s[t] += s[t + off];
        __syncthreads();
    }
    if (t == 0) g_bsum[blockIdx.x] = s[0];
}

__global__ __launch_bounds__(512) void scanB_k() {
    __shared__ int s[512];
    int t = threadIdx.x;
    int v = (t < NBLK) ? g_bsum[t] : 0;
    s[t] = v;
    __syncthreads();
    for (int off = 1; off < 512; off <<= 1) {
        int u = (t >= off) ? s[t - off] : 0;
        __syncthreads();
        s[t] += u;
        __syncthreads();
    }
    if (t < NBLK) g_bsum[t] = s[t] - v;   // exclusive
}

__global__ __launch_bounds__(256) void scanC_k() {
    __shared__ int s[256];
    int t = threadIdx.x;
    int idx = blockIdx.x * 256 + t;
    int v = (idx < NN) ? g_deg[idx] : 0;
    s[t] = v;
    __syncthreads();
    for (int off = 1; off < 256; off <<= 1) {
        int u = (t >= off) ? s[t - off] : 0;
        __syncthreads();
        s[t] += u;
        __syncthreads();
    }
    if (idx < NN) g_rowptr[idx] = g_bsum[blockIdx.x] + s[t] - v;
    if (idx == 0) g_rowptr[NN] = NE;
}

__global__ __launch_bounds__(256) void fill_k(const int* __restrict__ ei,
                                              const int* __restrict__ et) {
    int e = blockIdx.x * blockDim.x + threadIdx.x;
    if (e < NE) {
        int s = ei[e];
        int d = ei[NE + e];
        int t = et[e];
        int p = atomicAdd(&g_pos[d], 1);
        g_eidx[g_rowptr[d] + p] = s | (t << 17);
    }
}

// ---------------- 128x128-tile fp32 SGEMM, 8x8 split-fragment microtile ----------------
// mode 2: cols -> (r = c>>4): r<6 -> g_xt2[r], r==6 -> g_z + bias, r==7 skip
// mode 3: cols < 64 -> g_y[(row+rowOff)] + bias, cols >= 64 skip (B zero-padded there)
__global__ __launch_bounds__(256) void gemm128_k(
    const float* __restrict__ A, const float* __restrict__ B,
    const float* __restrict__ bias, float* __restrict__ C,
    int M, int K, int ldb, int mode, int rowOff)
{
    __shared__ __align__(16) float As[2][16][132];
    __shared__ __align__(16) float Bs[2][16][128];
    const int tid = threadIdx.x;
    const int tm4 = (tid >> 4) << 2;
    const int tn4 = (tid & 15) << 2;
    const int rowBase = blockIdx.y * 128;
    const int colBase = blockIdx.x * 128;

    const int ar = tid >> 2;
    const int ak = (tid & 3) << 2;
    const int bk = tid >> 4;
    const int bc = (tid & 15) << 3;

    float acc[8][8];
    #pragma unroll
    for (int i = 0; i < 8; i++)
        #pragma unroll
        for (int j = 0; j < 8; j++) acc[i][j] = 0.f;

    float4 pa0, pa1, pb0, pb1;

    {
        int r0 = rowBase + ar, r1 = rowBase + ar + 64;
        pa0 = (r0 < M) ? *reinterpret_cast<const float4*>(A + (size_t)r0 * K + ak)
                       : make_float4(0.f, 0.f, 0.f, 0.f);
        pa1 = (r1 < M) ? *reinterpret_cast<const float4*>(A + (size_t)r1 * K + ak)
                       : make_float4(0.f, 0.f, 0.f, 0.f);
        const float* bp = B + (size_t)bk * ldb + colBase + bc;
        pb0 = *reinterpret_cast<const float4*>(bp);
        pb1 = *reinterpret_cast<const float4*>(bp + 4);
    }
    {
        As[0][ak + 0][ar] = pa0.x; As[0][ak + 1][ar] = pa0.y;
        As[0][ak + 2][ar] = pa0.z; As[0][ak + 3][ar] = pa0.w;
        As[0][ak + 0][ar + 64] = pa1.x; As[0][ak + 1][ar + 64] = pa1.y;
        As[0][ak + 2][ar + 64] = pa1.z; As[0][ak + 3][ar + 64] = pa1.w;
        *reinterpret_cast<float4*>(&Bs[0][bk][bc]) = pb0;
        *reinterpret_cast<float4*>(&Bs[0][bk][bc + 4]) = pb1;
    }
    __syncthreads();

    const int nk = K >> 4;
    for (int ch = 1; ch < nk; ch++) {
        int k0 = ch << 4;
        {
            int r0 = rowBase + ar, r1 = rowBase + ar + 64;
            pa0 = (r0 < M) ? *reinterpret_cast<const float4*>(A + (size_t)r0 * K + k0 + ak)
                           : make_float4(0.f, 0.f, 0.f, 0.f);
            pa1 = (r1 < M) ? *reinterpret_cast<const float4*>(A + (size_t)r1 * K + k0 + ak)
                           : make_float4(0.f, 0.f, 0.f, 0.f);
            const float* bp = B + (size_t)(k0 + bk) * ldb + colBase + bc;
            pb0 = *reinterpret_cast<const float4*>(bp);
            pb1 = *reinterpret_cast<const float4*>(bp + 4);
        }
        int pbuf = (ch - 1) & 1;
        #pragma unroll
        for (int kk = 0; kk < 16; kk++) {
            float4 a0 = *reinterpret_cast<const float4*>(&As[pbuf][kk][tm4]);
            float4 a1 = *reinterpret_cast<const float4*>(&As[pbuf][kk][64 + tm4]);
            float4 b0 = *reinterpret_cast<const float4*>(&Bs[pbuf][kk][tn4]);
            float4 b1 = *reinterpret_cast<const float4*>(&Bs[pbuf][kk][64 + tn4]);
            float av[8] = {a0.x, a0.y, a0.z, a0.w, a1.x, a1.y, a1.z, a1.w};
            float bv[8] = {b0.x, b0.y, b0.z, b0.w, b1.x, b1.y, b1.z, b1.w};
            #pragma unroll
            for (int i = 0; i < 8; i++)
                #pragma unroll
                for (int j = 0; j < 8; j++)
                    acc[i][j] = fmaf(av[i], bv[j], acc[i][j]);
        }
        int buf = ch & 1;
        As[buf][ak + 0][ar] = pa0.x; As[buf][ak + 1][ar] = pa0.y;
        As[buf][ak + 2][ar] = pa0.z; As[buf][ak + 3][ar] = pa0.w;
        As[buf][ak + 0][ar + 64] = pa1.x; As[buf][ak + 1][ar + 64] = pa1.y;
        As[buf][ak + 2][ar + 64] = pa1.z; As[buf][ak + 3][ar + 64] = pa1.w;
        *reinterpret_cast<float4*>(&Bs[buf][bk][bc]) = pb0;
        *reinterpret_cast<float4*>(&Bs[buf][bk][bc + 4]) = pb1;
        __syncthreads();
    }
    {
        int pbuf = (nk - 1) & 1;
        #pragma unroll
        for (int kk = 0; kk < 16; kk++) {
            float4 a0 = *reinterpret_cast<const float4*>(&As[pbuf][kk][tm4]);
            float4 a1 = *reinterpret_cast<const float4*>(&As[pbuf][kk][64 + tm4]);
            float4 b0 = *reinterpret_cast<const float4*>(&Bs[pbuf][kk][tn4]);
            float4 b1 = *reinterpret_cast<const float4*>(&Bs[pbuf][kk][64 + tn4]);
            float av[8] = {a0.x, a0.y, a0.z, a0.w, a1.x, a1.y, a1.z, a1.w};
            float bv[8] = {b0.x, b0.y, b0.z, b0.w, b1.x, b1.y, b1.z, b1.w};
            #pragma unroll
            for (int i = 0; i < 8; i++)
                #pragma unroll
                for (int j = 0; j < 8; j++)
                    acc[i][j] = fmaf(av[i], bv[j], acc[i][j]);
        }
    }

    // ---- epilogue ----
    #pragma unroll
    for (int ri = 0; ri < 2; ri++) {
        #pragma unroll
        for (int i = 0; i < 4; i++) {
            int row = rowBase + ri * 64 + tm4 + i;
            if (row >= M) continue;
            #pragma unroll
            for (int cj = 0; cj < 2; cj++) {
                int gcol = colBase + cj * 64 + tn4;
                float4 v = make_float4(acc[ri * 4 + i][cj * 4 + 0],
                                       acc[ri * 4 + i][cj * 4 + 1],
                                       acc[ri * 4 + i][cj * 4 + 2],
                                       acc[ri * 4 + i][cj * 4 + 3]);
                if (mode == 2) {
                    int r = gcol >> 4, f = gcol & 15;
                    if (r < 6) {
                        *reinterpret_cast<float4*>(g_xt2 + ((size_t)r * NN + row) * 16 + f) = v;
                    } else if (r == 6) {
                        float4 bv = *reinterpret_cast<const float4*>(bias + f);
                        v.x += bv.x; v.y += bv.y; v.z += bv.z; v.w += bv.w;
                        *reinterpret_cast<float4*>(g_z + (size_t)row * 16 + f) = v;
                    }
                } else {  // mode 3: fused root -> g_y at global row
                    if (gcol < 64) {
                        float4 bv = *reinterpret_cast<const float4*>(bias + gcol);
                        v.x += bv.x; v.y += bv.y; v.z += bv.z; v.w += bv.w;
                        *reinterpret_cast<float4*>(
                            g_y + (size_t)(row + rowOff) * 64 + gcol) = v;
                    }
                }
            }
        }
    }
}

// ---------------- fp16 tensor-core GEMM core (plain-LDS fragments, documented layout) ----------------
__device__ __forceinline__ void mma16816(float* c, const uint32_t* a, uint32_t b0, uint32_t b1) {
    asm volatile("mma.sync.aligned.m16n8k16.row.col.f32.f16.f16.f32 "
                 "{%0,%1,%2,%3}, {%4,%5,%6,%7}, {%8,%9}, {%0,%1,%2,%3};\n"
                 : "+f"(c[0]), "+f"(c[1]), "+f"(c[2]), "+f"(c[3])
                 : "r"(a[0]), "r"(a[1]), "r"(a[2]), "r"(a[3]), "r"(b0), "r"(b1));
}

// layer-1 relation transforms: xt_h[r][row][o] = sum_k x_h[row][k] * W1ct_h[r*64+o][k]
__global__ __launch_bounds__(256) void hgemm_xt_k() {
    __shared__ __align__(16) __half As[128][72];
    __shared__ __align__(16) __half Bs[128][72];
    const int tid = threadIdx.x;
    const int lane = tid & 31;
    const int warp = tid >> 5;
    const int wm = warp >> 1;
    const int wn = warp & 1;
    const int rowBase = blockIdx.y * 128;
    const int colBase = blockIdx.x * 128;

    float acc[2][8][4];
    #pragma unroll
    for (int mt = 0; mt < 2; mt++)
        #pragma unroll
        for (int nt = 0; nt < 8; nt++)
            acc[mt][nt][0] = acc[mt][nt][1] = acc[mt][nt][2] = acc[mt][nt][3] = 0.f;

    const int ldrow = tid >> 1;
    const int ldhalf = tid & 1;

    for (int kc = 0; kc < 2; kc++) {
        if (kc) __syncthreads();
        {
            int grow = rowBase + ldrow;
            const uint4* src = reinterpret_cast<const uint4*>(
                g_x_h + (size_t)grow * 128 + kc * 64 + ldhalf * 32);
            uint4* dst = reinterpret_cast<uint4*>(&As[ldrow][ldhalf * 32]);
            #pragma unroll
            for (int i = 0; i < 4; i++) {
                uint4 v = make_uint4(0u, 0u, 0u, 0u);
                if (grow < NN) v = src[i];
                dst[i] = v;
            }
        }
        {
            const uint4* src = reinterpret_cast<const uint4*>(
                g_W1ct_h + (size_t)(colBase + ldrow) * 128 + kc * 64 + ldhalf * 32);
            uint4* dst = reinterpret_cast<uint4*>(&Bs[ldrow][ldhalf * 32]);
            #pragma unroll
            for (int i = 0; i < 4; i++) dst[i] = src[i];
        }
        __syncthreads();

        const int g = lane >> 2, t = lane & 3;
        #pragma unroll
        for (int s = 0; s < 4; s++) {
            const int k0 = s * 16 + 2 * t;
            uint32_t a[2][4];
            #pragma unroll
            for (int mt = 0; mt < 2; mt++) {
                int rb = wm * 32 + mt * 16;
                a[mt][0] = *reinterpret_cast<const uint32_t*>(&As[rb + g][k0]);
                a[mt][1] = *reinterpret_cast<const uint32_t*>(&As[rb + g + 8][k0]);
                a[mt][2] = *reinterpret_cast<const uint32_t*>(&As[rb + g][k0 + 8]);
                a[mt][3] = *reinterpret_cast<const uint32_t*>(&As[rb + g + 8][k0 + 8]);
            }
            uint32_t b[8][2];
            #pragma unroll
            for (int nt = 0; nt < 8; nt++) {
                int nb = wn * 64 + nt * 8;
                b[nt][0] = *reinterpret_cast<const uint32_t*>(&Bs[nb + g][k0]);
                b[nt][1] = *reinterpret_cast<const uint32_t*>(&Bs[nb + g][k0 + 8]);
            }
            #pragma unroll
            for (int mt = 0; mt < 2; mt++)
                #pragma unroll
                for (int nt = 0; nt < 8; nt++)
                    mma16816(acc[mt][nt], a[mt], b[nt][0], b[nt][1]);
        }
    }

    const int gid = lane >> 2, tig = lane & 3;
    #pragma unroll
    for (int mt = 0; mt < 2; mt++) {
        int grow0 = rowBase + wm * 32 + mt * 16 + gid;
        #pragma unroll
        for (int nt = 0; nt < 8; nt++) {
            int gn = colBase + wn * 64 + nt * 8 + tig * 2;
            int r = gn >> 6, f = gn & 63;
            if (grow0 < NN) {
                __half2 h = __floats2half2_rn(acc[mt][nt][0], acc[mt][nt][1]);
                *reinterpret_cast<__half2*>(g_xt_h + ((size_t)r * NN + grow0) * 64 + f) = h;
            }
            if (grow0 + 8 < NN) {
                __half2 h = __floats2half2_rn(acc[mt][nt][2], acc[mt][nt][3]);
                *reinterpret_cast<__half2*>(g_xt_h + ((size_t)r * NN + grow0 + 8) * 64 + f) = h;
            }
        }
    }
}

// fp16 projection: x_h[(row+rowOff)][0..127] = in_h[row][K] @ w_hᵀ + bias
// w_h n-major [o][K]; grid (1, ceil(M/128)); K in {128,256,512}
__global__ __launch_bounds__(256) void hgemm_proj_k(int M, int K, int inOff, int wOff,
                                                    const float* __restrict__ bias, int rowOff) {
    __shared__ __align__(16) __half As[128][72];
    __shared__ __align__(16) __half Bs[128][72];
    const int tid = threadIdx.x;
    const int lane = tid & 31;
    const int warp = tid >> 5;
    const int wm = warp >> 1;
    const int wn = warp & 1;
    const int rowBase = blockIdx.y * 128;

    float acc[2][8][4];
    #pragma unroll
    for (int mt = 0; mt < 2; mt++)
        #pragma unroll
        for (int nt = 0; nt < 8; nt++)
            acc[mt][nt][0] = acc[mt][nt][1] = acc[mt][nt][2] = acc[mt][nt][3] = 0.f;

    const int ldrow = tid >> 1;
    const int ldhalf = tid & 1;
    const __half* inBase = g_in_h + inOff;
    const __half* wBase  = g_w_h + wOff;

    const int nkc = K >> 6;
    for (int kc = 0; kc < nkc; kc++) {
        if (kc) __syncthreads();
        {
            int grow = rowBase + ldrow;
            const uint4* src = reinterpret_cast<const uint4*>(
                inBase + (size_t)grow * K + kc * 64 + ldhalf * 32);
            uint4* dst = reinterpret_cast<uint4*>(&As[ldrow][ldhalf * 32]);
            #pragma unroll
            for (int i = 0; i < 4; i++) {
                uint4 v = make_uint4(0u, 0u, 0u, 0u);
                if (grow < M) v = src[i];
                dst[i] = v;
            }
        }
        {
            const uint4* src = reinterpret_cast<const uint4*>(
                wBase + (size_t)ldrow * K + kc * 64 + ldhalf * 32);
            uint4* dst = reinterpret_cast<uint4*>(&Bs[ldrow][ldhalf * 32]);
            #pragma unroll
            for (int i = 0; i < 4; i++) dst[i] = src[i];
        }
        __syncthreads();

        const int g = lane >> 2, t = lane & 3;
        #pragma unroll
        for (int s = 0; s < 4; s++) {
            const int k0 = s * 16 + 2 * t;
            uint32_t a[2][4];
            #pragma unroll
            for (int mt = 0; mt < 2; mt++) {
                int rb = wm * 32 + mt * 16;
                a[mt][0] = *reinterpret_cast<const uint32_t*>(&As[rb + g][k0]);
                a[mt][1] = *reinterpret_cast<const uint32_t*>(&As[rb + g + 8][k0]);
                a[mt][2] = *reinterpret_cast<const uint32_t*>(&As[rb + g][k0 + 8]);
                a[mt][3] = *reinterpret_cast<const uint32_t*>(&As[rb + g + 8][k0 + 8]);
            }
            uint32_t b[8][2];
            #pragma unroll
            for (int nt = 0; nt < 8; nt++) {
                int nb = wn * 64 + nt * 8;
                b[nt][0] = *reinterpret_cast<const uint32_t*>(&Bs[nb + g][k0]);
                b[nt][1] = *reinterpret_cast<const uint32_t*>(&Bs[nb + g][k0 + 8]);
            }
            #pragma unroll
            for (int mt = 0; mt < 2; mt++)
                #pragma unroll
                for (int nt = 0; nt < 8; nt++)
                    mma16816(acc[mt][nt], a[mt], b[nt][0], b[nt][1]);
        }
    }

    const int gid = lane >> 2, tig = lane & 3;
    #pragma unroll
    for (int mt = 0; mt < 2; mt++) {
        int lrow0 = rowBase + wm * 32 + mt * 16 + gid;
        #pragma unroll
        for (int nt = 0; nt < 8; nt++) {
            int gn = wn * 64 + nt * 8 + tig * 2;   // 0..127 output feature
            float b0 = bias[gn], b1 = bias[gn + 1];
            if (lrow0 < M) {
                __half2 h = __floats2half2_rn(acc[mt][nt][0] + b0, acc[mt][nt][1] + b1);
                *reinterpret_cast<__half2*>(
                    g_x_h + (size_t)(lrow0 + rowOff) * 128 + gn) = h;
            }
            if (lrow0 + 8 < M) {
                __half2 h = __floats2half2_rn(acc[mt][nt][2] + b0, acc[mt][nt][3] + b1);
                *reinterpret_cast<__half2*>(
                    g_x_h + (size_t)(lrow0 + 8 + rowOff) * 128 + gn) = h;
            }
        }
    }
}

// ---------------- edge aggregation (CSR by dst, no float atomics) ----------------
__device__ __forceinline__ float sel_inv(int t, float i0, float i1, float i2,
                                         float i3, float i4, float i5) {
    float w = i5;
    w = (t == 4) ? i4 : w;
    w = (t == 3) ? i3 : w;
    w = (t == 2) ? i2 : w;
    w = (t == 1) ? i1 : w;
    w = (t == 0) ? i0 : w;
    return w;
}

// layer 1: F=64 fp16, one warp per dst, each lane owns 2 features (__half2)
__global__ __launch_bounds__(256) void agg1_k() {
    int gw = (blockIdx.x * blockDim.x + threadIdx.x) >> 5;
    int lane = threadIdx.x & 31;
    if (gw >= NN) return;
    const int dst = gw;
    const int beg = g_rowptr[dst];
    const int end = g_rowptr[dst + 1];
    const float i0 = g_inv[dst],          i1 = g_inv[NN + dst],     i2 = g_inv[2 * NN + dst],
                i3 = g_inv[3 * NN + dst], i4 = g_inv[4 * NN + dst], i5 = g_inv[5 * NN + dst];
    const __half2* __restrict__ base = reinterpret_cast<const __half2*>(g_xt_h);
    float ax = 0.f, ay = 0.f;
    int e = beg;
    for (; e + 8 <= end; e += 8) {
        #pragma unroll
        for (int u = 0; u < 8; u++) {
            int p = g_eidx[e + u];
            __half2 h = base[(size_t)((p >> 17) * NN + (p & 131071)) * 32 + lane];
            float2 v = __half22float2(h);
            float w = sel_inv(p >> 17, i0, i1, i2, i3, i4, i5);
            ax = fmaf(w, v.x, ax); ay = fmaf(w, v.y, ay);
        }
    }
    for (; e < end; e++) {
        int p = g_eidx[e];
        __half2 h = base[(size_t)((p >> 17) * NN + (p & 131071)) * 32 + lane];
        float2 v = __half22float2(h);
        float w = sel_inv(p >> 17, i0, i1, i2, i3, i4, i5);
        ax = fmaf(w, v.x, ax); ay = fmaf(w, v.y, ay);
    }
    float2* yrow = reinterpret_cast<float2*>(g_y) + (size_t)dst * 32 + lane;
    float2 cur = *yrow;
    cur.x += ax; cur.y += ay;
    *yrow = cur;
}

// layer 2: F=16 fp32, 16-thread group per dst
__global__ __launch_bounds__(256) void agg2_k() {
    int g = (blockIdx.x * blockDim.x + threadIdx.x) >> 4;
    int lane = threadIdx.x & 15;
    if (g >= NN) return;
    const int dst = g;
    const int beg = g_rowptr[dst];
    const int end = g_rowptr[dst + 1];
    const float i0 = g_inv[dst],          i1 = g_inv[NN + dst],     i2 = g_inv[2 * NN + dst],
                i3 = g_inv[3 * NN + dst], i4 = g_inv[4 * NN + dst], i5 = g_inv[5 * NN + dst];
    float acc = 0.f;
    int e = beg;
    for (; e + 4 <= end; e += 4) {
        int p0 = g_eidx[e], p1 = g_eidx[e + 1], p2 = g_eidx[e + 2], p3 = g_eidx[e + 3];
        float v0 = g_xt2[(size_t)((p0 >> 17) * NN + (p0 & 131071)) * 16 + lane];
        float v1 = g_xt2[(size_t)((p1 >> 17) * NN + (p1 & 131071)) * 16 + lane];
        float v2 = g_xt2[(size_t)((p2 >> 17) * NN + (p2 & 131071)) * 16 + lane];
        float v3 = g_xt2[(size_t)((p3 >> 17) * NN + (p3 & 131071)) * 16 + lane];
        acc = fmaf(sel_inv(p0 >> 17, i0, i1, i2, i3, i4, i5), v0, acc);
        acc = fmaf(sel_inv(p1 >> 17, i0, i1, i2, i3, i4, i5), v1, acc);
        acc = fmaf(sel_inv(p2 >> 17, i0, i1, i2, i3, i4, i5), v2, acc);
        acc = fmaf(sel_inv(p3 >> 17, i0, i1, i2, i3, i4, i5), v3, acc);
    }
    for (; e < end; e++) {
        int p = g_eidx[e];
        float v = g_xt2[(size_t)((p >> 17) * NN + (p & 131071)) * 16 + lane];
        acc = fmaf(sel_inv(p >> 17, i0, i1, i2, i3, i4, i5), v, acc);
    }
    g_z[(size_t)dst * 16 + lane] += acc;
}

// ---------------- softmax over first 30000 rows ----------------
__global__ __launch_bounds__(256) void softmax_k(float* __restrict__ out) {
    int r = blockIdx.x * blockDim.x + threadIdx.x;
    if (r >= 30000) return;
    const float4* zr = reinterpret_cast<const float4*>(g_z + (size_t)r * 16);
    float vals[16];
    *reinterpret_cast<float4*>(&vals[0])  = zr[0];
    *reinterpret_cast<float4*>(&vals[4])  = zr[1];
    *reinterpret_cast<float4*>(&vals[8])  = zr[2];
    *reinterpret_cast<float4*>(&vals[12]) = zr[3];
    float m = vals[0];
    #pragma unroll
    for (int i = 1; i < 16; i++) m = fmaxf(m, vals[i]);
    float s = 0.f;
    #pragma unroll
    for (int i = 0; i < 16; i++) { vals[i] = __expf(vals[i] - m); s += vals[i]; }
    float inv = 1.f / s;
    float4* o = reinterpret_cast<float4*>(out + (size_t)r * 16);
    o[0] = make_float4(vals[0] * inv,  vals[1] * inv,  vals[2] * inv,  vals[3] * inv);
    o[1] = make_float4(vals[4] * inv,  vals[5] * inv,  vals[6] * inv,  vals[7] * inv);
    o[2] = make_float4(vals[8] * inv,  vals[9] * inv,  vals[10] * inv, vals[11] * inv);
    o[3] = make_float4(vals[12] * inv, vals[13] * inv, vals[14] * inv, vals[15] * inv);
}

// ---------------- launcher ----------------
extern "C" void kernel_launch(void* const* d_in, const int* in_sizes, int n_in,
                              void* d_out, int out_size) {
    const float* x0     = (const float*)d_in[0];
    const float* x1     = (const float*)d_in[1];
    const float* x2     = (const float*)d_in[2];
    const float* lw0    = (const float*)d_in[3];
    const float* lb0    = (const float*)d_in[4];
    const float* lw1    = (const float*)d_in[5];
    const float* lb1    = (const float*)d_in[6];
    const float* lw2    = (const float*)d_in[7];
    const float* lb2    = (const float*)d_in[8];
    const float* bases1 = (const float*)d_in[9];
    const float* comp1  = (const float*)d_in[10];
    const float* root1  = (const float*)d_in[11];
    const float* bias1  = (const float*)d_in[12];
    const float* bases2 = (const float*)d_in[13];
    const float* comp2  = (const float*)d_in[14];
    const float* root2  = (const float*)d_in[15];
    const float* bias2  = (const float*)d_in[16];
    const int*   eidx   = (const int*)d_in[17];
    const int*   etyp   = (const int*)d_in[18];

    float *py, *pWf, *pbf, *pW2c;
    cudaGetSymbolAddress((void**)&py,   g_y);
    cudaGetSymbolAddress((void**)&pWf,  g_Wf);
    cudaGetSymbolAddress((void**)&pbf,  g_bf);
    cudaGetSymbolAddress((void**)&pW2c, g_W2c);

    const int CONV4 = (M0 * K0 + M1 * K1 + M2 * K2) / 4;
    const int PREPW = 128 * (K0 + K1 + K2) + (K0 + K1 + K2) * 64 + 192;

    convIn_k<<<(CONV4 + 255) / 256, 256>>>(x0, x1, x2);                                     // 0
    prepW_k<<<(PREPW + 255) / 256, 256>>>(lw0, lw1, lw2, lb0, lb1, lb2, root1, bias1);      // 1
    zero_k<<<(6 * NN + 255) / 256, 256>>>();                                                // 2
    hgemm_proj_k<<<dim3(1, (M1 + 127) / 128), 256>>>(M1, K1, IN1_OFF, W1_OFF, lb1, M0);     // 3 (profiled)
    compWc_k<<<(128 * 384 + 64 * 128 + 255) / 256, 256>>>(comp1, bases1, comp2, bases2, root2); // 4
    count_k<<<(NE + 255) / 256, 256>>>(eidx, etyp);                                         // 5
    prep_k<<<(6 * NN + 255) / 256, 256>>>();                                                // 6
    scanA_k<<<NBLK, 256>>>();                                                               // 7
    scanB_k<<<1, 512>>>();                                                                  // 8
    scanC_k<<<NBLK, 256>>>();                                                               // 9
    fill_k<<<(NE + 255) / 256, 256>>>(eidx, etyp);                                          // 10
    hgemm_proj_k<<<dim3(1, (M0 + 127) / 128), 256>>>(M0, K0, IN0_OFF, W0_OFF, lb0, 0);      // 11
    hgemm_proj_k<<<dim3(1, (M2 + 127) / 128), 256>>>(M2, K2, IN2_OFF, W2_OFF, lb2, M0 + M1);// 12

    // layer-1 relation transforms (tensor cores)
    hgemm_xt_k<<<dim3(3, (NN + 127) / 128), 256>>>();                                       // 13

    // fused root path (exact fp32, from original inputs)
    gemm128_k<<<dim3(1, (M0 + 127) / 128), 256>>>(x0, pWf + WF0_OFF, pbf,       nullptr,
                                                  M0, K0, 128, 3, 0);                       // 14
    gemm128_k<<<dim3(1, (M1 + 127) / 128), 256>>>(x1, pWf + WF1_OFF, pbf + 64,  nullptr,
                                                  M1, K1, 128, 3, M0);                      // 15
    gemm128_k<<<dim3(1, (M2 + 127) / 128), 256>>>(x2, pWf + WF2_OFF, pbf + 128, nullptr,
                                                  M2, K2, 128, 3, M0 + M1);                 // 16

    agg1_k<<<NN / 8, 256>>>();                                                              // 17

    // layer-2 fused fp32 (mode 2)
    gemm128_k<<<dim3(1, (NN + 127) / 128), 256>>>(py, pW2c, bias2, nullptr,
                                                  NN, 64, 128, 2, 0);                       // 18

    agg2_k<<<NN / 16, 256>>>();                                                             // 19

    softmax_k<<<(30000 + 255) / 256, 256>>>((float*)d_out);                                 // 20
}

// round 15
// speedup vs baseline: 1.1179x; 1.1179x over previous
#include <cuda_runtime.h>
#include <cuda_fp16.h>
#include <cstdint>
#include <cstddef>

#define NN 100000
#define NE 1600000
#define NBLK 391   // ceil(NN/256)

// segment geometry
#define M0 30000
#define M1 50000
#define M2 20000
#define K0 256
#define K1 512
#define K2 128
#define IN0_OFF 0
#define IN1_OFF (M0 * K0)
#define IN2_OFF (M0 * K0 + M1 * K1)
#define W0_OFF 0
#define W1_OFF (128 * K0)
#define W2_OFF (128 * K0 + 128 * K1)
// compact 64-wide fused-root weight row offsets (rows = global in-dim)
#define WFR0 0
#define WFR1 K0
#define WFR2 (K0 + K1)

// ---------------- scratch (static __device__, no allocations) ----------------
__device__ __align__(128) __half g_in_h[M0 * K0 + M1 * K1 + M2 * K2];  // fp16 inputs
__device__ __align__(128) __half g_w_h[128 * (K0 + K1 + K2)];          // fp16 lin weights, n-major [o][i]
__device__ __align__(128) __half g_x_h[NN * 128];        // fp16 projected features
__device__ __align__(128) __half g_xt_h[6 * NN * 64];    // per-relation transformed, layer 1 (fp16)
__device__ __align__(128) float  g_y[NN * 64];           // layer-1 output
__device__ __align__(128) float  g_xt2[6 * NN * 16];     // per-relation transformed, layer 2
__device__ __align__(128) float  g_z[NN * 16];           // layer-2 output
__device__ __align__(128) float  g_inv[6 * NN];          // 1/max(cnt,1)
__device__ int   g_cnt[6 * NN];
__device__ int   g_deg[NN];
__device__ int   g_pos[NN];
__device__ int   g_bsum[NBLK];
__device__ int   g_rowptr[NN + 1];
__device__ int   g_eidx[NE];                             // packed src | (et<<17)
__device__ __align__(128) __half g_W1ct_h[384 * 128];    // fp16 n-major: [(r*64+o)][k]
__device__ __align__(128) float  g_Wf[(K0 + K1 + K2) * 64];   // fused root weights, compact [i][o]
__device__ __align__(128) float  g_bf[3 * 64];           // fused root bias per segment
__device__ __align__(128) float  g_W2c[64 * 128];        // [k][r*16+o], r=0..5 rels, 6=root, 7=pad

// ---------------- convert inputs to fp16 ----------------
__global__ __launch_bounds__(256) void convIn_k(const float* __restrict__ x0,
                                                const float* __restrict__ x1,
                                                const float* __restrict__ x2) {
    const int TOT4 = (M0 * K0 + M1 * K1 + M2 * K2) / 4;
    int idx = blockIdx.x * blockDim.x + threadIdx.x;
    if (idx >= TOT4) return;
    int e = idx * 4;
    const float* src;
    int off;
    if (e < IN1_OFF)      { src = x0; off = e; }
    else if (e < IN2_OFF) { src = x1; off = e - IN1_OFF; }
    else                  { src = x2; off = e - IN2_OFF; }
    float4 v = *reinterpret_cast<const float4*>(src + off);
    __half2 h0 = __floats2half2_rn(v.x, v.y);
    __half2 h1 = __floats2half2_rn(v.z, v.w);
    __half2* dst = reinterpret_cast<__half2*>(g_in_h + e);
    dst[0] = h0; dst[1] = h1;
}

// ---------------- weight prep: fp16 lin weights, compact fused root weights + bias ----------------
__global__ __launch_bounds__(256) void prepW_k(const float* __restrict__ lw0,
                                               const float* __restrict__ lw1,
                                               const float* __restrict__ lw2,
                                               const float* __restrict__ lb0,
                                               const float* __restrict__ lb1,
                                               const float* __restrict__ lb2,
                                               const float* __restrict__ root1,
                                               const float* __restrict__ bias1) {
    const int NW = 128 * (K0 + K1 + K2);
    const int NF = (K0 + K1 + K2) * 64;
    int idx = blockIdx.x * blockDim.x + threadIdx.x;
    if (idx < NW) {
        float v;
        if (idx < W1_OFF)       v = lw0[idx];
        else if (idx < W2_OFF)  v = lw1[idx - W1_OFF];
        else                    v = lw2[idx - W2_OFF];
        g_w_h[idx] = __float2half(v);
    } else if (idx < NW + NF) {
        int j = idx - NW;
        int i = j >> 6, o = j & 63;             // i = global in-dim index 0..895
        const float* lw; int K, ioff;
        if (i < K0)            { lw = lw0; K = K0; ioff = i;            }
        else if (i < K0 + K1)  { lw = lw1; K = K1; ioff = i - K0;       }
        else                   { lw = lw2; K = K2; ioff = i - K0 - K1;  }
        float s = 0.f;
        #pragma unroll 8
        for (int k = 0; k < 128; k++)
            s = fmaf(lw[k * K + ioff], root1[k * 64 + o], s);
        g_Wf[(size_t)i * 64 + o] = s;
    } else if (idx < NW + NF + 192) {
        int j = idx - NW - NF;
        int s = j >> 6, o = j & 63;
        const float* lb = (s == 0) ? lb0 : (s == 1) ? lb1 : lb2;
        float acc = bias1[o];
        #pragma unroll 8
        for (int k = 0; k < 128; k++)
            acc = fmaf(lb[k], root1[k * 64 + o], acc);
        g_bf[s * 64 + o] = acc;
    }
}

// merged basis-composition for both layers
__global__ __launch_bounds__(256) void compWc_k(const float* __restrict__ comp1,
                                                const float* __restrict__ bases1,
                                                const float* __restrict__ comp2,
                                                const float* __restrict__ bases2,
                                                const float* __restrict__ root2) {
    int idx = blockIdx.x * blockDim.x + threadIdx.x;
    if (idx < 128 * 384) {
        int i = idx / 384, c = idx - i * 384;
        int r = c >> 6, o = c & 63;
        float s = 0.f;
        #pragma unroll 6
        for (int b = 0; b < 30; b++)
            s = fmaf(comp1[r * 30 + b], bases1[b * 8192 + i * 64 + o], s);
        g_W1ct_h[(size_t)c * 128 + i] = __float2half(s);
    } else if (idx < 128 * 384 + 64 * 128) {
        int j = idx - 128 * 384;
        int k = j >> 7, c = j & 127;
        int r = c >> 4, o = c & 15;
        float s = 0.f;
        if (r < 6) {
            #pragma unroll 6
            for (int b = 0; b < 30; b++)
                s = fmaf(comp2[r * 30 + b], bases2[b * 1024 + k * 16 + o], s);
        } else if (r == 6) {
            s = root2[k * 16 + o];
        }
        g_W2c[j] = s;
    }
}

__global__ __launch_bounds__(256) void zero_k() {
    int i = blockIdx.x * blockDim.x + threadIdx.x;
    if (i < 6 * NN) g_cnt[i] = 0;
    if (i < NN) g_pos[i] = 0;
}

__global__ __launch_bounds__(256) void count_k(const int* __restrict__ ei,
                                               const int* __restrict__ et) {
    int e = blockIdx.x * blockDim.x + threadIdx.x;
    if (e < NE) {
        int dst = ei[NE + e];
        int t = et[e];
        atomicAdd(&g_cnt[t * NN + dst], 1);
    }
}

__global__ __launch_bounds__(256) void prep_k() {
    int i = blockIdx.x * blockDim.x + threadIdx.x;
    if (i < 6 * NN) {
        int c = g_cnt[i];
        g_inv[i] = 1.0f / (float)(c > 1 ? c : 1);
    }
    if (i < NN) {
        int d = 0;
        #pragma unroll
        for (int r = 0; r < 6; r++) d += g_cnt[r * NN + i];
        g_deg[i] = d;
    }
}

// ---- 3-phase parallel scan of g_deg -> g_rowptr ----
__global__ __launch_bounds__(256) void scanA_k() {
    __shared__ int s[256];
    int t = threadIdx.x;
    int idx = blockIdx.x * 256 + t;
    int v = (idx < NN) ? g_deg[idx] : 0;
    s[t] = v;
    __syncthreads();
    for (int off = 128; off > 0; off >>= 1) {
        if (t < off) s[t] += s[t + off];
        __syncthreads();
    }
    if (t == 0) g_bsum[blockIdx.x] = s[0];
}

__global__ __launch_bounds__(512) void scanB_k() {
    __shared__ int s[512];
    int t = threadIdx.x;
    int v = (t < NBLK) ? g_bsum[t] : 0;
    s[t] = v;
    __syncthreads();
    for (int off = 1; off < 512; off <<= 1) {
        int u = (t >= off) ? s[t - off] : 0;
        __syncthreads();
        s[t] += u;
        __syncthreads();
    }
    if (t < NBLK) g_bsum[t] = s[t] - v;
}

__global__ __launch_bounds__(256) void scanC_k() {
    __shared__ int s[256];
    int t = threadIdx.x;
    int idx = blockIdx.x * 256 + t;
    int v = (idx < NN) ? g_deg[idx] : 0;
    s[t] = v;
    __syncthreads();
    for (int off = 1; off < 256; off <<= 1) {
        int u = (t >= off) ? s[t - off] : 0;
        __syncthreads();
        s[t] += u;
        __syncthreads();
    }
    if (idx < NN) g_rowptr[idx] = g_bsum[blockIdx.x] + s[t] - v;
    if (idx == 0) g_rowptr[NN] = NE;
}

__global__ __launch_bounds__(256) void fill_k(const int* __restrict__ ei,
                                              const int* __restrict__ et) {
    int e = blockIdx.x * blockDim.x + threadIdx.x;
    if (e < NE) {
        int s = ei[e];
        int d = ei[NE + e];
        int t = et[e];
        int p = atomicAdd(&g_pos[d], 1);
        g_eidx[g_rowptr[d] + p] = s | (t << 17);
    }
}

// ---------------- 128x128-tile fp32 SGEMM (layer-2 only, mode 2 epilogue) ----------------
__global__ __launch_bounds__(256) void gemm128_k(
    const float* __restrict__ A, const float* __restrict__ B,
    const float* __restrict__ bias, int M, int K, int ldb)
{
    __shared__ __align__(16) float As[2][16][132];
    __shared__ __align__(16) float Bs[2][16][128];
    const int tid = threadIdx.x;
    const int tm4 = (tid >> 4) << 2;
    const int tn4 = (tid & 15) << 2;
    const int rowBase = blockIdx.y * 128;
    const int colBase = blockIdx.x * 128;

    const int ar = tid >> 2;
    const int ak = (tid & 3) << 2;
    const int bk = tid >> 4;
    const int bc = (tid & 15) << 3;

    float acc[8][8];
    #pragma unroll
    for (int i = 0; i < 8; i++)
        #pragma unroll
        for (int j = 0; j < 8; j++) acc[i][j] = 0.f;

    float4 pa0, pa1, pb0, pb1;

    {
        int r0 = rowBase + ar, r1 = rowBase + ar + 64;
        pa0 = (r0 < M) ? *reinterpret_cast<const float4*>(A + (size_t)r0 * K + ak)
                       : make_float4(0.f, 0.f, 0.f, 0.f);
        pa1 = (r1 < M) ? *reinterpret_cast<const float4*>(A + (size_t)r1 * K + ak)
                       : make_float4(0.f, 0.f, 0.f, 0.f);
        const float* bp = B + (size_t)bk * ldb + colBase + bc;
        pb0 = *reinterpret_cast<const float4*>(bp);
        pb1 = *reinterpret_cast<const float4*>(bp + 4);
    }
    {
        As[0][ak + 0][ar] = pa0.x; As[0][ak + 1][ar] = pa0.y;
        As[0][ak + 2][ar] = pa0.z; As[0][ak + 3][ar] = pa0.w;
        As[0][ak + 0][ar + 64] = pa1.x; As[0][ak + 1][ar + 64] = pa1.y;
        As[0][ak + 2][ar + 64] = pa1.z; As[0][ak + 3][ar + 64] = pa1.w;
        *reinterpret_cast<float4*>(&Bs[0][bk][bc]) = pb0;
        *reinterpret_cast<float4*>(&Bs[0][bk][bc + 4]) = pb1;
    }
    __syncthreads();

    const int nk = K >> 4;
    for (int ch = 1; ch < nk; ch++) {
        int k0 = ch << 4;
        {
            int r0 = rowBase + ar, r1 = rowBase + ar + 64;
            pa0 = (r0 < M) ? *reinterpret_cast<const float4*>(A + (size_t)r0 * K + k0 + ak)
                           : make_float4(0.f, 0.f, 0.f, 0.f);
            pa1 = (r1 < M) ? *reinterpret_cast<const float4*>(A + (size_t)r1 * K + k0 + ak)
                           : make_float4(0.f, 0.f, 0.f, 0.f);
            const float* bp = B + (size_t)(k0 + bk) * ldb + colBase + bc;
            pb0 = *reinterpret_cast<const float4*>(bp);
            pb1 = *reinterpret_cast<const float4*>(bp + 4);
        }
        int pbuf = (ch - 1) & 1;
        #pragma unroll
        for (int kk = 0; kk < 16; kk++) {
            float4 a0 = *reinterpret_cast<const float4*>(&As[pbuf][kk][tm4]);
            float4 a1 = *reinterpret_cast<const float4*>(&As[pbuf][kk][64 + tm4]);
            float4 b0 = *reinterpret_cast<const float4*>(&Bs[pbuf][kk][tn4]);
            float4 b1 = *reinterpret_cast<const float4*>(&Bs[pbuf][kk][64 + tn4]);
            float av[8] = {a0.x, a0.y, a0.z, a0.w, a1.x, a1.y, a1.z, a1.w};
            float bv[8] = {b0.x, b0.y, b0.z, b0.w, b1.x, b1.y, b1.z, b1.w};
            #pragma unroll
            for (int i = 0; i < 8; i++)
                #pragma unroll
                for (int j = 0; j < 8; j++)
                    acc[i][j] = fmaf(av[i], bv[j], acc[i][j]);
        }
        int buf = ch & 1;
        As[buf][ak + 0][ar] = pa0.x; As[buf][ak + 1][ar] = pa0.y;
        As[buf][ak + 2][ar] = pa0.z; As[buf][ak + 3][ar] = pa0.w;
        As[buf][ak + 0][ar + 64] = pa1.x; As[buf][ak + 1][ar + 64] = pa1.y;
        As[buf][ak + 2][ar + 64] = pa1.z; As[buf][ak + 3][ar + 64] = pa1.w;
        *reinterpret_cast<float4*>(&Bs[buf][bk][bc]) = pb0;
        *reinterpret_cast<float4*>(&Bs[buf][bk][bc + 4]) = pb1;
        __syncthreads();
    }
    {
        int pbuf = (nk - 1) & 1;
        #pragma unroll
        for (int kk = 0; kk < 16; kk++) {
            float4 a0 = *reinterpret_cast<const float4*>(&As[pbuf][kk][tm4]);
            float4 a1 = *reinterpret_cast<const float4*>(&As[pbuf][kk][64 + tm4]);
            float4 b0 = *reinterpret_cast<const float4*>(&Bs[pbuf][kk][tn4]);
            float4 b1 = *reinterpret_cast<const float4*>(&Bs[pbuf][kk][64 + tn4]);
            float av[8] = {a0.x, a0.y, a0.z, a0.w, a1.x, a1.y, a1.z, a1.w};
            float bv[8] = {b0.x, b0.y, b0.z, b0.w, b1.x, b1.y, b1.z, b1.w};
            #pragma unroll
            for (int i = 0; i < 8; i++)
                #pragma unroll
                for (int j = 0; j < 8; j++)
                    acc[i][j] = fmaf(av[i], bv[j], acc[i][j]);
        }
    }

    // mode-2 epilogue: r<6 -> g_xt2[r], r==6 -> g_z + bias, r==7 skip
    #pragma unroll
    for (int ri = 0; ri < 2; ri++) {
        #pragma unroll
        for (int i = 0; i < 4; i++) {
            int row = rowBase + ri * 64 + tm4 + i;
            if (row >= M) continue;
            #pragma unroll
            for (int cj = 0; cj < 2; cj++) {
                int gcol = colBase + cj * 64 + tn4;
                float4 v = make_float4(acc[ri * 4 + i][cj * 4 + 0],
                                       acc[ri * 4 + i][cj * 4 + 1],
                                       acc[ri * 4 + i][cj * 4 + 2],
                                       acc[ri * 4 + i][cj * 4 + 3]);
                int r = gcol >> 4, f = gcol & 15;
                if (r < 6) {
                    *reinterpret_cast<float4*>(g_xt2 + ((size_t)r * NN + row) * 16 + f) = v;
                } else if (r == 6) {
                    float4 bv = *reinterpret_cast<const float4*>(bias + f);
                    v.x += bv.x; v.y += bv.y; v.z += bv.z; v.w += bv.w;
                    *reinterpret_cast<float4*>(g_z + (size_t)row * 16 + f) = v;
                }
            }
        }
    }
}

// ---------------- fused-root fp32 GEMM: 256x64 tiles, no wasted columns ----------------
// g_y[(row+rowOff)][o] = A[row][K] @ Wf[K][64] + bias[o]
__global__ __launch_bounds__(256) void gemmRoot_k(
    const float* __restrict__ A, const float* __restrict__ Wf,
    const float* __restrict__ bias, int M, int K, int rowOff)
{
    __shared__ __align__(16) float As[2][16][264];   // [k][row], padded
    __shared__ __align__(16) float Bs[2][16][64];    // [k][o]
    const int tid = threadIdx.x;
    const int ty = tid >> 3;          // 0..31 -> rows {ty*4+i, 128+ty*4+i}
    const int tx = tid & 7;           // 0..7  -> cols {tx*4+j, 32+tx*4+j}
    const int rowBase = blockIdx.y * 256;

    const int bk = tid >> 4;          // 0..15
    const int bc = (tid & 15) << 2;   // 0..60

    float acc[8][8];
    #pragma unroll
    for (int i = 0; i < 8; i++)
        #pragma unroll
        for (int j = 0; j < 8; j++) acc[i][j] = 0.f;

    float4 pa[4];
    float4 pb;

    // prologue: load chunk 0
    {
        int r = rowBase + tid;
        #pragma unroll
        for (int q = 0; q < 4; q++)
            pa[q] = (r < M) ? *reinterpret_cast<const float4*>(A + (size_t)r * K + q * 4)
                            : make_float4(0.f, 0.f, 0.f, 0.f);
        pb = *reinterpret_cast<const float4*>(Wf + (size_t)bk * 64 + bc);
    }
    {
        #pragma unroll
        for (int q = 0; q < 4; q++) {
            As[0][q * 4 + 0][tid] = pa[q].x;
            As[0][q * 4 + 1][tid] = pa[q].y;
            As[0][q * 4 + 2][tid] = pa[q].z;
            As[0][q * 4 + 3][tid] = pa[q].w;
        }
        *reinterpret_cast<float4*>(&Bs[0][bk][bc]) = pb;
    }
    __syncthreads();

    const int nk = K >> 4;
    for (int ch = 1; ch < nk; ch++) {
        int k0 = ch << 4;
        {
            int r = rowBase + tid;
            #pragma unroll
            for (int q = 0; q < 4; q++)
                pa[q] = (r < M) ? *reinterpret_cast<const float4*>(A + (size_t)r * K + k0 + q * 4)
                                : make_float4(0.f, 0.f, 0.f, 0.f);
            pb = *reinterpret_cast<const float4*>(Wf + (size_t)(k0 + bk) * 64 + bc);
        }
        int pbuf = (ch - 1) & 1;
        #pragma unroll
        for (int kk = 0; kk < 16; kk++) {
            float4 a0 = *reinterpret_cast<const float4*>(&As[pbuf][kk][ty << 2]);
            float4 a1 = *reinterpret_cast<const float4*>(&As[pbuf][kk][128 + (ty << 2)]);
            float4 b0 = *reinterpret_cast<const float4*>(&Bs[pbuf][kk][tx << 2]);
            float4 b1 = *reinterpret_cast<const float4*>(&Bs[pbuf][kk][32 + (tx << 2)]);
            float av[8] = {a0.x, a0.y, a0.z, a0.w, a1.x, a1.y, a1.z, a1.w};
            float bv[8] = {b0.x, b0.y, b0.z, b0.w, b1.x, b1.y, b1.z, b1.w};
            #pragma unroll
            for (int i = 0; i < 8; i++)
                #pragma unroll
                for (int j = 0; j < 8; j++)
                    acc[i][j] = fmaf(av[i], bv[j], acc[i][j]);
        }
        int buf = ch & 1;
        #pragma unroll
        for (int q = 0; q < 4; q++) {
            As[buf][q * 4 + 0][tid] = pa[q].x;
            As[buf][q * 4 + 1][tid] = pa[q].y;
            As[buf][q * 4 + 2][tid] = pa[q].z;
            As[buf][q * 4 + 3][tid] = pa[q].w;
        }
        *reinterpret_cast<float4*>(&Bs[buf][bk][bc]) = pb;
        __syncthreads();
    }
    {
        int pbuf = (nk - 1) & 1;
        #pragma unroll
        for (int kk = 0; kk < 16; kk++) {
            float4 a0 = *reinterpret_cast<const float4*>(&As[pbuf][kk][ty << 2]);
            float4 a1 = *reinterpret_cast<const float4*>(&As[pbuf][kk][128 + (ty << 2)]);
            float4 b0 = *reinterpret_cast<const float4*>(&Bs[pbuf][kk][tx << 2]);
            float4 b1 = *reinterpret_cast<const float4*>(&Bs[pbuf][kk][32 + (tx << 2)]);
            float av[8] = {a0.x, a0.y, a0.z, a0.w, a1.x, a1.y, a1.z, a1.w};
            float bv[8] = {b0.x, b0.y, b0.z, b0.w, b1.x, b1.y, b1.z, b1.w};
            #pragma unroll
            for (int i = 0; i < 8; i++)
                #pragma unroll
                for (int j = 0; j < 8; j++)
                    acc[i][j] = fmaf(av[i], bv[j], acc[i][j]);
        }
    }

    // epilogue: rows {rowBase + ri*128 + ty*4 + i}, cols {cj*32 + tx*4}
    #pragma unroll
    for (int ri = 0; ri < 2; ri++) {
        #pragma unroll
        for (int i = 0; i < 4; i++) {
            int row = rowBase + ri * 128 + (ty << 2) + i;
            if (row >= M) continue;
            #pragma unroll
            for (int cj = 0; cj < 2; cj++) {
                int c = cj * 32 + (tx << 2);
                float4 bv = *reinterpret_cast<const float4*>(bias + c);
                float4 v = make_float4(acc[ri * 4 + i][cj * 4 + 0] + bv.x,
                                       acc[ri * 4 + i][cj * 4 + 1] + bv.y,
                                       acc[ri * 4 + i][cj * 4 + 2] + bv.z,
                                       acc[ri * 4 + i][cj * 4 + 3] + bv.w);
                *reinterpret_cast<float4*>(g_y + (size_t)(row + rowOff) * 64 + c) = v;
            }
        }
    }
}

// ---------------- fp16 tensor-core GEMM core ----------------
__device__ __forceinline__ void mma16816(float* c, const uint32_t* a, uint32_t b0, uint32_t b1) {
    asm volatile("mma.sync.aligned.m16n8k16.row.col.f32.f16.f16.f32 "
                 "{%0,%1,%2,%3}, {%4,%5,%6,%7}, {%8,%9}, {%0,%1,%2,%3};\n"
                 : "+f"(c[0]), "+f"(c[1]), "+f"(c[2]), "+f"(c[3])
                 : "r"(a[0]), "r"(a[1]), "r"(a[2]), "r"(a[3]), "r"(b0), "r"(b1));
}

// layer-1 relation transforms: xt_h[r][row][o] = sum_k x_h[row][k] * W1ct_h[r*64+o][k]
__global__ __launch_bounds__(256) void hgemm_xt_k() {
    __shared__ __align__(16) __half As[128][72];
    __shared__ __align__(16) __half Bs[128][72];
    const int tid = threadIdx.x;
    const int lane = tid & 31;
    const int warp = tid >> 5;
    const int wm = warp >> 1;
    const int wn = warp & 1;
    const int rowBase = blockIdx.y * 128;
    const int colBase = blockIdx.x * 128;

    float acc[2][8][4];
    #pragma unroll
    for (int mt = 0; mt < 2; mt++)
        #pragma unroll
        for (int nt = 0; nt < 8; nt++)
            acc[mt][nt][0] = acc[mt][nt][1] = acc[mt][nt][2] = acc[mt][nt][3] = 0.f;

    const int ldrow = tid >> 1;
    const int ldhalf = tid & 1;

    for (int kc = 0; kc < 2; kc++) {
        if (kc) __syncthreads();
        {
            int grow = rowBase + ldrow;
            const uint4* src = reinterpret_cast<const uint4*>(
                g_x_h + (size_t)grow * 128 + kc * 64 + ldhalf * 32);
            uint4* dst = reinterpret_cast<uint4*>(&As[ldrow][ldhalf * 32]);
            #pragma unroll
            for (int i = 0; i < 4; i++) {
                uint4 v = make_uint4(0u, 0u, 0u, 0u);
                if (grow < NN) v = src[i];
                dst[i] = v;
            }
        }
        {
            const uint4* src = reinterpret_cast<const uint4*>(
                g_W1ct_h + (size_t)(colBase + ldrow) * 128 + kc * 64 + ldhalf * 32);
            uint4* dst = reinterpret_cast<uint4*>(&Bs[ldrow][ldhalf * 32]);
            #pragma unroll
            for (int i = 0; i < 4; i++) dst[i] = src[i];
        }
        __syncthreads();

        const int g = lane >> 2, t = lane & 3;
        #pragma unroll
        for (int s = 0; s < 4; s++) {
            const int k0 = s * 16 + 2 * t;
            uint32_t a[2][4];
            #pragma unroll
            for (int mt = 0; mt < 2; mt++) {
                int rb = wm * 32 + mt * 16;
                a[mt][0] = *reinterpret_cast<const uint32_t*>(&As[rb + g][k0]);
                a[mt][1] = *reinterpret_cast<const uint32_t*>(&As[rb + g + 8][k0]);
                a[mt][2] = *reinterpret_cast<const uint32_t*>(&As[rb + g][k0 + 8]);
                a[mt][3] = *reinterpret_cast<const uint32_t*>(&As[rb + g + 8][k0 + 8]);
            }
            uint32_t b[8][2];
            #pragma unroll
            for (int nt = 0; nt < 8; nt++) {
                int nb = wn * 64 + nt * 8;
                b[nt][0] = *reinterpret_cast<const uint32_t*>(&Bs[nb + g][k0]);
                b[nt][1] = *reinterpret_cast<const uint32_t*>(&Bs[nb + g][k0 + 8]);
            }
            #pragma unroll
            for (int mt = 0; mt < 2; mt++)
                #pragma unroll
                for (int nt = 0; nt < 8; nt++)
                    mma16816(acc[mt][nt], a[mt], b[nt][0], b[nt][1]);
        }
    }

    const int gid = lane >> 2, tig = lane & 3;
    #pragma unroll
    for (int mt = 0; mt < 2; mt++) {
        int grow0 = rowBase + wm * 32 + mt * 16 + gid;
        #pragma unroll
        for (int nt = 0; nt < 8; nt++) {
            int gn = colBase + wn * 64 + nt * 8 + tig * 2;
            int r = gn >> 6, f = gn & 63;
            if (grow0 < NN) {
                __half2 h = __floats2half2_rn(acc[mt][nt][0], acc[mt][nt][1]);
                *reinterpret_cast<__half2*>(g_xt_h + ((size_t)r * NN + grow0) * 64 + f) = h;
            }
            if (grow0 + 8 < NN) {
                __half2 h = __floats2half2_rn(acc[mt][nt][2], acc[mt][nt][3]);
                *reinterpret_cast<__half2*>(g_xt_h + ((size_t)r * NN + grow0 + 8) * 64 + f) = h;
            }
        }
    }
}

// fp16 projection: x_h[(row+rowOff)][0..127] = in_h[row][K] @ w_hᵀ + bias
__global__ __launch_bounds__(256) void hgemm_proj_k(int M, int K, int inOff, int wOff,
                                                    const float* __restrict__ bias, int rowOff) {
    __shared__ __align__(16) __half As[128][72];
    __shared__ __align__(16) __half Bs[128][72];
    const int tid = threadIdx.x;
    const int lane = tid & 31;
    const int warp = tid >> 5;
    const int wm = warp >> 1;
    const int wn = warp & 1;
    const int rowBase = blockIdx.y * 128;

    float acc[2][8][4];
    #pragma unroll
    for (int mt = 0; mt < 2; mt++)
        #pragma unroll
        for (int nt = 0; nt < 8; nt++)
            acc[mt][nt][0] = acc[mt][nt][1] = acc[mt][nt][2] = acc[mt][nt][3] = 0.f;

    const int ldrow = tid >> 1;
    const int ldhalf = tid & 1;
    const __half* inBase = g_in_h + inOff;
    const __half* wBase  = g_w_h + wOff;

    const int nkc = K >> 6;
    for (int kc = 0; kc < nkc; kc++) {
        if (kc) __syncthreads();
        {
            int grow = rowBase + ldrow;
            const uint4* src = reinterpret_cast<const uint4*>(
                inBase + (size_t)grow * K + kc * 64 + ldhalf * 32);
            uint4* dst = reinterpret_cast<uint4*>(&As[ldrow][ldhalf * 32]);
            #pragma unroll
            for (int i = 0; i < 4; i++) {
                uint4 v = make_uint4(0u, 0u, 0u, 0u);
                if (grow < M) v = src[i];
                dst[i] = v;
            }
        }
        {
            const uint4* src = reinterpret_cast<const uint4*>(
                wBase + (size_t)ldrow * K + kc * 64 + ldhalf * 32);
            uint4* dst = reinterpret_cast<uint4*>(&Bs[ldrow][ldhalf * 32]);
            #pragma unroll
            for (int i = 0; i < 4; i++) dst[i] = src[i];
        }
        __syncthreads();

        const int g = lane >> 2, t = lane & 3;
        #pragma unroll
        for (int s = 0; s < 4; s++) {
            const int k0 = s * 16 + 2 * t;
            uint32_t a[2][4];
            #pragma unroll
            for (int mt = 0; mt < 2; mt++) {
                int rb = wm * 32 + mt * 16;
                a[mt][0] = *reinterpret_cast<const uint32_t*>(&As[rb + g][k0]);
                a[mt][1] = *reinterpret_cast<const uint32_t*>(&As[rb + g + 8][k0]);
                a[mt][2] = *reinterpret_cast<const uint32_t*>(&As[rb + g][k0 + 8]);
                a[mt][3] = *reinterpret_cast<const uint32_t*>(&As[rb + g + 8][k0 + 8]);
            }
            uint32_t b[8][2];
            #pragma unroll
            for (int nt = 0; nt < 8; nt++) {
                int nb = wn * 64 + nt * 8;
                b[nt][0] = *reinterpret_cast<const uint32_t*>(&Bs[nb + g][k0]);
                b[nt][1] = *reinterpret_cast<const uint32_t*>(&Bs[nb + g][k0 + 8]);
            }
            #pragma unroll
            for (int mt = 0; mt < 2; mt++)
                #pragma unroll
                for (int nt = 0; nt < 8; nt++)
                    mma16816(acc[mt][nt], a[mt], b[nt][0], b[nt][1]);
        }
    }

    const int gid = lane >> 2, tig = lane & 3;
    #pragma unroll
    for (int mt = 0; mt < 2; mt++) {
        int lrow0 = rowBase + wm * 32 + mt * 16 + gid;
        #pragma unroll
        for (int nt = 0; nt < 8; nt++) {
            int gn = wn * 64 + nt * 8 + tig * 2;
            float b0 = bias[gn], b1 = bias[gn + 1];
            if (lrow0 < M) {
                __half2 h = __floats2half2_rn(acc[mt][nt][0] + b0, acc[mt][nt][1] + b1);
                *reinterpret_cast<__half2*>(
                    g_x_h + (size_t)(lrow0 + rowOff) * 128 + gn) = h;
            }
            if (lrow0 + 8 < M) {
                __half2 h = __floats2half2_rn(acc[mt][nt][2] + b0, acc[mt][nt][3] + b1);
                *reinterpret_cast<__half2*>(
                    g_x_h + (size_t)(lrow0 + 8 + rowOff) * 128 + gn) = h;
            }
        }
    }
}

// ---------------- edge aggregation (CSR by dst, no float atomics) ----------------
__device__ __forceinline__ float sel_inv(int t, float i0, float i1, float i2,
                                         float i3, float i4, float i5) {
    float w = i5;
    w = (t == 4) ? i4 : w;
    w = (t == 3) ? i3 : w;
    w = (t == 2) ? i2 : w;
    w = (t == 1) ? i1 : w;
    w = (t == 0) ? i0 : w;
    return w;
}

// layer 1: F=64 fp16, one warp per dst
__global__ __launch_bounds__(256) void agg1_k() {
    int gw = (blockIdx.x * blockDim.x + threadIdx.x) >> 5;
    int lane = threadIdx.x & 31;
    if (gw >= NN) return;
    const int dst = gw;
    const int beg = g_rowptr[dst];
    const int end = g_rowptr[dst + 1];
    const float i0 = g_inv[dst],          i1 = g_inv[NN + dst],     i2 = g_inv[2 * NN + dst],
                i3 = g_inv[3 * NN + dst], i4 = g_inv[4 * NN + dst], i5 = g_inv[5 * NN + dst];
    const __half2* __restrict__ base = reinterpret_cast<const __half2*>(g_xt_h);
    float ax = 0.f, ay = 0.f;
    int e = beg;
    for (; e + 8 <= end; e += 8) {
        #pragma unroll
        for (int u = 0; u < 8; u++) {
            int p = g_eidx[e + u];
            __half2 h = base[(size_t)((p >> 17) * NN + (p & 131071)) * 32 + lane];
            float2 v = __half22float2(h);
            float w = sel_inv(p >> 17, i0, i1, i2, i3, i4, i5);
            ax = fmaf(w, v.x, ax); ay = fmaf(w, v.y, ay);
        }
    }
    for (; e < end; e++) {
        int p = g_eidx[e];
        __half2 h = base[(size_t)((p >> 17) * NN + (p & 131071)) * 32 + lane];
        float2 v = __half22float2(h);
        float w = sel_inv(p >> 17, i0, i1, i2, i3, i4, i5);
        ax = fmaf(w, v.x, ax); ay = fmaf(w, v.y, ay);
    }
    float2* yrow = reinterpret_cast<float2*>(g_y) + (size_t)dst * 32 + lane;
    float2 cur = *yrow;
    cur.x += ax; cur.y += ay;
    *yrow = cur;
}

// layer 2: F=16 fp32, 16-thread group per dst
__global__ __launch_bounds__(256) void agg2_k() {
    int g = (blockIdx.x * blockDim.x + threadIdx.x) >> 4;
    int lane = threadIdx.x & 15;
    if (g >= NN) return;
    const int dst = g;
    const int beg = g_rowptr[dst];
    const int end = g_rowptr[dst + 1];
    const float i0 = g_inv[dst],          i1 = g_inv[NN + dst],     i2 = g_inv[2 * NN + dst],
                i3 = g_inv[3 * NN + dst], i4 = g_inv[4 * NN + dst], i5 = g_inv[5 * NN + dst];
    float acc = 0.f;
    int e = beg;
    for (; e + 4 <= end; e += 4) {
        int p0 = g_eidx[e], p1 = g_eidx[e + 1], p2 = g_eidx[e + 2], p3 = g_eidx[e + 3];
        float v0 = g_xt2[(size_t)((p0 >> 17) * NN + (p0 & 131071)) * 16 + lane];
        float v1 = g_xt2[(size_t)((p1 >> 17) * NN + (p1 & 131071)) * 16 + lane];
        float v2 = g_xt2[(size_t)((p2 >> 17) * NN + (p2 & 131071)) * 16 + lane];
        float v3 = g_xt2[(size_t)((p3 >> 17) * NN + (p3 & 131071)) * 16 + lane];
        acc = fmaf(sel_inv(p0 >> 17, i0, i1, i2, i3, i4, i5), v0, acc);
        acc = fmaf(sel_inv(p1 >> 17, i0, i1, i2, i3, i4, i5), v1, acc);
        acc = fmaf(sel_inv(p2 >> 17, i0, i1, i2, i3, i4, i5), v2, acc);
        acc = fmaf(sel_inv(p3 >> 17, i0, i1, i2, i3, i4, i5), v3, acc);
    }
    for (; e < end; e++) {
        int p = g_eidx[e];
        float v = g_xt2[(size_t)((p >> 17) * NN + (p & 131071)) * 16 + lane];
        acc = fmaf(sel_inv(p >> 17, i0, i1, i2, i3, i4, i5), v, acc);
    }
    g_z[(size_t)dst * 16 + lane] += acc;
}

// ---------------- softmax over first 30000 rows ----------------
__global__ __launch_bounds__(256) void softmax_k(float* __restrict__ out) {
    int r = blockIdx.x * blockDim.x + threadIdx.x;
    if (r >= 30000) return;
    const float4* zr = reinterpret_cast<const float4*>(g_z + (size_t)r * 16);
    float vals[16];
    *reinterpret_cast<float4*>(&vals[0])  = zr[0];
    *reinterpret_cast<float4*>(&vals[4])  = zr[1];
    *reinterpret_cast<float4*>(&vals[8])  = zr[2];
    *reinterpret_cast<float4*>(&vals[12]) = zr[3];
    float m = vals[0];
    #pragma unroll
    for (int i = 1; i < 16; i++) m = fmaxf(m, vals[i]);
    float s = 0.f;
    #pragma unroll
    for (int i = 0; i < 16; i++) { vals[i] = __expf(vals[i] - m); s += vals[i]; }
    float inv = 1.f / s;
    float4* o = reinterpret_cast<float4*>(out + (size_t)r * 16);
    o[0] = make_float4(vals[0] * inv,  vals[1] * inv,  vals[2] * inv,  vals[3] * inv);
    o[1] = make_float4(vals[4] * inv,  vals[5] * inv,  vals[6] * inv,  vals[7] * inv);
    o[2] = make_float4(vals[8] * inv,  vals[9] * inv,  vals[10] * inv, vals[11] * inv);
    o[3] = make_float4(vals[12] * inv, vals[13] * inv, vals[14] * inv, vals[15] * inv);
}

// ---------------- launcher ----------------
extern "C" void kernel_launch(void* const* d_in, const int* in_sizes, int n_in,
                              void* d_out, int out_size) {
    const float* x0     = (const float*)d_in[0];
    const float* x1     = (const float*)d_in[1];
    const float* x2     = (const float*)d_in[2];
    const float* lw0    = (const float*)d_in[3];
    const float* lb0    = (const float*)d_in[4];
    const float* lw1    = (const float*)d_in[5];
    const float* lb1    = (const float*)d_in[6];
    const float* lw2    = (const float*)d_in[7];
    const float* lb2    = (const float*)d_in[8];
    const float* bases1 = (const float*)d_in[9];
    const float* comp1  = (const float*)d_in[10];
    const float* root1  = (const float*)d_in[11];
    const float* bias1  = (const float*)d_in[12];
    const float* bases2 = (const float*)d_in[13];
    const float* comp2  = (const float*)d_in[14];
    const float* root2  = (const float*)d_in[15];
    const float* bias2  = (const float*)d_in[16];
    const int*   eidx   = (const int*)d_in[17];
    const int*   etyp   = (const int*)d_in[18];

    float *py, *pWf, *pbf, *pW2c;
    cudaGetSymbolAddress((void**)&py,   g_y);
    cudaGetSymbolAddress((void**)&pWf,  g_Wf);
    cudaGetSymbolAddress((void**)&pbf,  g_bf);
    cudaGetSymbolAddress((void**)&pW2c, g_W2c);

    const int CONV4 = (M0 * K0 + M1 * K1 + M2 * K2) / 4;
    const int PREPW = 128 * (K0 + K1 + K2) + (K0 + K1 + K2) * 64 + 192;

    convIn_k<<<(CONV4 + 255) / 256, 256>>>(x0, x1, x2);                                     // 0
    prepW_k<<<(PREPW + 255) / 256, 256>>>(lw0, lw1, lw2, lb0, lb1, lb2, root1, bias1);      // 1
    zero_k<<<(6 * NN + 255) / 256, 256>>>();                                                // 2
    hgemm_proj_k<<<dim3(1, (M1 + 127) / 128), 256>>>(M1, K1, IN1_OFF, W1_OFF, lb1, M0);     // 3 (profiled)
    compWc_k<<<(128 * 384 + 64 * 128 + 255) / 256, 256>>>(comp1, bases1, comp2, bases2, root2); // 4
    count_k<<<(NE + 255) / 256, 256>>>(eidx, etyp);                                         // 5
    prep_k<<<(6 * NN + 255) / 256, 256>>>();                                                // 6
    scanA_k<<<NBLK, 256>>>();                                                               // 7
    scanB_k<<<1, 512>>>();                                                                  // 8
    scanC_k<<<NBLK, 256>>>();                                                               // 9
    fill_k<<<(NE + 255) / 256, 256>>>(eidx, etyp);                                          // 10
    hgemm_proj_k<<<dim3(1, (M0 + 127) / 128), 256>>>(M0, K0, IN0_OFF, W0_OFF, lb0, 0);      // 11
    hgemm_proj_k<<<dim3(1, (M2 + 127) / 128), 256>>>(M2, K2, IN2_OFF, W2_OFF, lb2, M0 + M1);// 12

    // layer-1 relation transforms (tensor cores)
    hgemm_xt_k<<<dim3(3, (NN + 127) / 128), 256>>>();                                       // 13

    // fused root path (exact fp32, from original inputs; no wasted columns)
    gemmRoot_k<<<dim3(1, (M0 + 255) / 256), 256>>>(x0, pWf + WFR0 * 64, pbf,       M0, K0, 0);       // 14
    gemmRoot_k<<<dim3(1, (M1 + 255) / 256), 256>>>(x1, pWf + WFR1 * 64, pbf + 64,  M1, K1, M0);      // 15
    gemmRoot_k<<<dim3(1, (M2 + 255) / 256), 256>>>(x2, pWf + WFR2 * 64, pbf + 128, M2, K2, M0 + M1); // 16

    agg1_k<<<NN / 8, 256>>>();                                                              // 17

    // layer-2 fused fp32
    gemm128_k<<<dim3(1, (NN + 127) / 128), 256>>>(py, pW2c, bias2, NN, 64, 128);            // 18

    agg2_k<<<NN / 16, 256>>>();                                                             // 19

    softmax_k<<<(30000 + 255) / 256, 256>>>((float*)d_out);                                 // 20
}

// round 17
// speedup vs baseline: 1.1516x; 1.0302x over previous
#include <cuda_runtime.h>
#include <cuda_fp16.h>
#include <cstdint>
#include <cstddef>

#define NN 100000
#define NE 1600000
#define NBLK 391   // ceil(NN/256)

// segment geometry
#define M0 30000
#define M1 50000
#define M2 20000
#define K0 256
#define K1 512
#define K2 128
#define IN0_OFF 0
#define IN1_OFF (M0 * K0)
#define IN2_OFF (M0 * K0 + M1 * K1)
#define W0_OFF 0
#define W1_OFF (128 * K0)
#define W2_OFF (128 * K0 + 128 * K1)
// compact 64-wide fused-root weight row offsets (rows = global in-dim)
#define WFR0 0
#define WFR1 K0
#define WFR2 (K0 + K1)

// ---------------- scratch (static __device__, no allocations) ----------------
__device__ __align__(128) __half g_in_h[M0 * K0 + M1 * K1 + M2 * K2];  // fp16 inputs
__device__ __align__(128) __half g_w_h[128 * (K0 + K1 + K2)];          // fp16 lin weights, n-major [o][i]
__device__ __align__(128) __half g_x_h[NN * 128];        // fp16 projected features
__device__ __align__(128) __half g_xt_h[6 * NN * 64];    // per-relation transformed, layer 1 (fp16)
__device__ __align__(128) float  g_y[NN * 64];           // layer-1 output
__device__ __align__(128) float  g_xt2[6 * NN * 16];     // per-relation transformed, layer 2
__device__ __align__(128) float  g_z[NN * 16];           // layer-2 output
__device__ __align__(128) float  g_inv[6 * NN];          // 1/max(cnt,1)
__device__ int   g_cnt[6 * NN];
__device__ int   g_deg[NN];
__device__ int   g_pos[NN];
__device__ int   g_bsum[NBLK];
__device__ int   g_rowptr[NN + 1];
__device__ int   g_eidx[NE];                             // packed src | (et<<17)
__device__ __align__(128) __half g_W1ct_h[384 * 128];    // fp16 n-major: [(r*64+o)][k]
__device__ __align__(128) float  g_Wf[(K0 + K1 + K2) * 64];   // fused root weights, compact [i][o]
__device__ __align__(128) float  g_bf[3 * 64];           // fused root bias per segment
__device__ __align__(128) float  g_W2c[64 * 128];        // [k][r*16+o], r=0..5 rels, 6=root, 7=pad

// ---------------- cp.async helpers ----------------
__device__ __forceinline__ void cpasync16(uint32_t smem_addr, const void* gptr, int src_bytes) {
    asm volatile("cp.async.cg.shared.global [%0], [%1], 16, %2;\n"
                 :: "r"(smem_addr), "l"(gptr), "r"(src_bytes));
}
__device__ __forceinline__ void cpasync_commit() {
    asm volatile("cp.async.commit_group;\n" ::: "memory");
}
__device__ __forceinline__ void cpasync_wait1() {
    asm volatile("cp.async.wait_group 1;\n" ::: "memory");
}
__device__ __forceinline__ void cpasync_wait0() {
    asm volatile("cp.async.wait_group 0;\n" ::: "memory");
}

// ---------------- convert inputs to fp16 ----------------
__global__ __launch_bounds__(256) void convIn_k(const float* __restrict__ x0,
                                                const float* __restrict__ x1,
                                                const float* __restrict__ x2) {
    const int TOT4 = (M0 * K0 + M1 * K1 + M2 * K2) / 4;
    int idx = blockIdx.x * blockDim.x + threadIdx.x;
    if (idx >= TOT4) return;
    int e = idx * 4;
    const float* src;
    int off;
    if (e < IN1_OFF)      { src = x0; off = e; }
    else if (e < IN2_OFF) { src = x1; off = e - IN1_OFF; }
    else                  { src = x2; off = e - IN2_OFF; }
    float4 v = *reinterpret_cast<const float4*>(src + off);
    __half2 h0 = __floats2half2_rn(v.x, v.y);
    __half2 h1 = __floats2half2_rn(v.z, v.w);
    __half2* dst = reinterpret_cast<__half2*>(g_in_h + e);
    dst[0] = h0; dst[1] = h1;
}

// ---------------- weight prep: fp16 lin weights, compact fused root weights + bias ----------------
__global__ __launch_bounds__(256) void prepW_k(const float* __restrict__ lw0,
                                               const float* __restrict__ lw1,
                                               const float* __restrict__ lw2,
                                               const float* __restrict__ lb0,
                                               const float* __restrict__ lb1,
                                               const float* __restrict__ lb2,
                                               const float* __restrict__ root1,
                                               const float* __restrict__ bias1) {
    const int NW = 128 * (K0 + K1 + K2);
    const int NF = (K0 + K1 + K2) * 64;
    int idx = blockIdx.x * blockDim.x + threadIdx.x;
    if (idx < NW) {
        float v;
        if (idx < W1_OFF)       v = lw0[idx];
        else if (idx < W2_OFF)  v = lw1[idx - W1_OFF];
        else                    v = lw2[idx - W2_OFF];
        g_w_h[idx] = __float2half(v);
    } else if (idx < NW + NF) {
        int j = idx - NW;
        int i = j >> 6, o = j & 63;
        const float* lw; int K, ioff;
        if (i < K0)            { lw = lw0; K = K0; ioff = i;            }
        else if (i < K0 + K1)  { lw = lw1; K = K1; ioff = i - K0;       }
        else                   { lw = lw2; K = K2; ioff = i - K0 - K1;  }
        float s = 0.f;
        #pragma unroll 8
        for (int k = 0; k < 128; k++)
            s = fmaf(lw[k * K + ioff], root1[k * 64 + o], s);
        g_Wf[(size_t)i * 64 + o] = s;
    } else if (idx < NW + NF + 192) {
        int j = idx - NW - NF;
        int s = j >> 6, o = j & 63;
        const float* lb = (s == 0) ? lb0 : (s == 1) ? lb1 : lb2;
        float acc = bias1[o];
        #pragma unroll 8
        for (int k = 0; k < 128; k++)
            acc = fmaf(lb[k], root1[k * 64 + o], acc);
        g_bf[s * 64 + o] = acc;
    }
}

// merged basis-composition for both layers
__global__ __launch_bounds__(256) void compWc_k(const float* __restrict__ comp1,
                                                const float* __restrict__ bases1,
                                                const float* __restrict__ comp2,
                                                const float* __restrict__ bases2,
                                                const float* __restrict__ root2) {
    int idx = blockIdx.x * blockDim.x + threadIdx.x;
    if (idx < 128 * 384) {
        int i = idx / 384, c = idx - i * 384;
        int r = c >> 6, o = c & 63;
        float s = 0.f;
        #pragma unroll 6
        for (int b = 0; b < 30; b++)
            s = fmaf(comp1[r * 30 + b], bases1[b * 8192 + i * 64 + o], s);
        g_W1ct_h[(size_t)c * 128 + i] = __float2half(s);
    } else if (idx < 128 * 384 + 64 * 128) {
        int j = idx - 128 * 384;
        int k = j >> 7, c = j & 127;
        int r = c >> 4, o = c & 15;
        float s = 0.f;
        if (r < 6) {
            #pragma unroll 6
            for (int b = 0; b < 30; b++)
                s = fmaf(comp2[r * 30 + b], bases2[b * 1024 + k * 16 + o], s);
        } else if (r == 6) {
            s = root2[k * 16 + o];
        }
        g_W2c[j] = s;
    }
}

__global__ __launch_bounds__(256) void zero_k() {
    int i = blockIdx.x * blockDim.x + threadIdx.x;
    if (i < 6 * NN) g_cnt[i] = 0;
    if (i < NN) g_pos[i] = 0;
}

__global__ __launch_bounds__(256) void count_k(const int* __restrict__ ei,
                                               const int* __restrict__ et) {
    int e = blockIdx.x * blockDim.x + threadIdx.x;
    if (e < NE) {
        int dst = ei[NE + e];
        int t = et[e];
        atomicAdd(&g_cnt[t * NN + dst], 1);
    }
}

__global__ __launch_bounds__(256) void prep_k() {
    int i = blockIdx.x * blockDim.x + threadIdx.x;
    if (i < 6 * NN) {
        int c = g_cnt[i];
        g_inv[i] = 1.0f / (float)(c > 1 ? c : 1);
    }
    if (i < NN) {
        int d = 0;
        #pragma unroll
        for (int r = 0; r < 6; r++) d += g_cnt[r * NN + i];
        g_deg[i] = d;
    }
}

// ---- 3-phase parallel scan of g_deg -> g_rowptr ----
__global__ __launch_bounds__(256) void scanA_k() {
    __shared__ int s[256];
    int t = threadIdx.x;
    int idx = blockIdx.x * 256 + t;
    int v = (idx < NN) ? g_deg[idx] : 0;
    s[t] = v;
    __syncthreads();
    for (int off = 128; off > 0; off >>= 1) {
        if (t < off) s[t] += s[t + off];
        __syncthreads();
    }
    if (t == 0) g_bsum[blockIdx.x] = s[0];
}

__global__ __launch_bounds__(512) void scanB_k() {
    __shared__ int s[512];
    int t = threadIdx.x;
    int v = (t < NBLK) ? g_bsum[t] : 0;
    s[t] = v;
    __syncthreads();
    for (int off = 1; off < 512; off <<= 1) {
        int u = (t >= off) ? s[t - off] : 0;
        __syncthreads();
        s[t] += u;
        __syncthreads();
    }
    if (t < NBLK) g_bsum[t] = s[t] - v;
}

__global__ __launch_bounds__(256) void scanC_k() {
    __shared__ int s[256];
    int t = threadIdx.x;
    int idx = blockIdx.x * 256 + t;
    int v = (idx < NN) ? g_deg[idx] : 0;
    s[t] = v;
    __syncthreads();
    for (int off = 1; off < 256; off <<= 1) {
        int u = (t >= off) ? s[t - off] : 0;
        __syncthreads();
        s[t] += u;
        __syncthreads();
    }
    if (idx < NN) g_rowptr[idx] = g_bsum[blockIdx.x] + s[t] - v;
    if (idx == 0) g_rowptr[NN] = NE;
}

__global__ __launch_bounds__(256) void fill_k(const int* __restrict__ ei,
                                              const int* __restrict__ et) {
    int e = blockIdx.x * blockDim.x + threadIdx.x;
    if (e < NE) {
        int s = ei[e];
        int d = ei[NE + e];
        int t = et[e];
        int p = atomicAdd(&g_pos[d], 1);
        g_eidx[g_rowptr[d] + p] = s | (t << 17);
    }
}

// ---------------- 128x128-tile fp32 SGEMM (layer-2 only, mode 2 epilogue) ----------------
__global__ __launch_bounds__(256) void gemm128_k(
    const float* __restrict__ A, const float* __restrict__ B,
    const float* __restrict__ bias, int M, int K, int ldb)
{
    __shared__ __align__(16) float As[2][16][132];
    __shared__ __align__(16) float Bs[2][16][128];
    const int tid = threadIdx.x;
    const int tm4 = (tid >> 4) << 2;
    const int tn4 = (tid & 15) << 2;
    const int rowBase = blockIdx.y * 128;
    const int colBase = blockIdx.x * 128;

    const int ar = tid >> 2;
    const int ak = (tid & 3) << 2;
    const int bk = tid >> 4;
    const int bc = (tid & 15) << 3;

    float acc[8][8];
    #pragma unroll
    for (int i = 0; i < 8; i++)
        #pragma unroll
        for (int j = 0; j < 8; j++) acc[i][j] = 0.f;

    float4 pa0, pa1, pb0, pb1;

    {
        int r0 = rowBase + ar, r1 = rowBase + ar + 64;
        pa0 = (r0 < M) ? *reinterpret_cast<const float4*>(A + (size_t)r0 * K + ak)
                       : make_float4(0.f, 0.f, 0.f, 0.f);
        pa1 = (r1 < M) ? *reinterpret_cast<const float4*>(A + (size_t)r1 * K + ak)
                       : make_float4(0.f, 0.f, 0.f, 0.f);
        const float* bp = B + (size_t)bk * ldb + colBase + bc;
        pb0 = *reinterpret_cast<const float4*>(bp);
        pb1 = *reinterpret_cast<const float4*>(bp + 4);
    }
    {
        As[0][ak + 0][ar] = pa0.x; As[0][ak + 1][ar] = pa0.y;
        As[0][ak + 2][ar] = pa0.z; As[0][ak + 3][ar] = pa0.w;
        As[0][ak + 0][ar + 64] = pa1.x; As[0][ak + 1][ar + 64] = pa1.y;
        As[0][ak + 2][ar + 64] = pa1.z; As[0][ak + 3][ar + 64] = pa1.w;
        *reinterpret_cast<float4*>(&Bs[0][bk][bc]) = pb0;
        *reinterpret_cast<float4*>(&Bs[0][bk][bc + 4]) = pb1;
    }
    __syncthreads();

    const int nk = K >> 4;
    for (int ch = 1; ch < nk; ch++) {
        int k0 = ch << 4;
        {
            int r0 = rowBase + ar, r1 = rowBase + ar + 64;
            pa0 = (r0 < M) ? *reinterpret_cast<const float4*>(A + (size_t)r0 * K + k0 + ak)
                           : make_float4(0.f, 0.f, 0.f, 0.f);
            pa1 = (r1 < M) ? *reinterpret_cast<const float4*>(A + (size_t)r1 * K + k0 + ak)
                           : make_float4(0.f, 0.f, 0.f, 0.f);
            const float* bp = B + (size_t)(k0 + bk) * ldb + colBase + bc;
            pb0 = *reinterpret_cast<const float4*>(bp);
            pb1 = *reinterpret_cast<const float4*>(bp + 4);
        }
        int pbuf = (ch - 1) & 1;
        #pragma unroll
        for (int kk = 0; kk < 16; kk++) {
            float4 a0 = *reinterpret_cast<const float4*>(&As[pbuf][kk][tm4]);
            float4 a1 = *reinterpret_cast<const float4*>(&As[pbuf][kk][64 + tm4]);
            float4 b0 = *reinterpret_cast<const float4*>(&Bs[pbuf][kk][tn4]);
            float4 b1 = *reinterpret_cast<const float4*>(&Bs[pbuf][kk][64 + tn4]);
            float av[8] = {a0.x, a0.y, a0.z, a0.w, a1.x, a1.y, a1.z, a1.w};
            float bv[8] = {b0.x, b0.y, b0.z, b0.w, b1.x, b1.y, b1.z, b1.w};
            #pragma unroll
            for (int i = 0; i < 8; i++)
                #pragma unroll
                for (int j = 0; j < 8; j++)
                    acc[i][j] = fmaf(av[i], bv[j], acc[i][j]);
        }
        int buf = ch & 1;
        As[buf][ak + 0][ar] = pa0.x; As[buf][ak + 1][ar] = pa0.y;
        As[buf][ak + 2][ar] = pa0.z; As[buf][ak + 3][ar] = pa0.w;
        As[buf][ak + 0][ar + 64] = pa1.x; As[buf][ak + 1][ar + 64] = pa1.y;
        As[buf][ak + 2][ar + 64] = pa1.z; As[buf][ak + 3][ar + 64] = pa1.w;
        *reinterpret_cast<float4*>(&Bs[buf][bk][bc]) = pb0;
        *reinterpret_cast<float4*>(&Bs[buf][bk][bc + 4]) = pb1;
        __syncthreads();
    }
    {
        int pbuf = (nk - 1) & 1;
        #pragma unroll
        for (int kk = 0; kk < 16; kk++) {
            float4 a0 = *reinterpret_cast<const float4*>(&As[pbuf][kk][tm4]);
            float4 a1 = *reinterpret_cast<const float4*>(&As[pbuf][kk][64 + tm4]);
            float4 b0 = *reinterpret_cast<const float4*>(&Bs[pbuf][kk][tn4]);
            float4 b1 = *reinterpret_cast<const float4*>(&Bs[pbuf][kk][64 + tn4]);
            float av[8] = {a0.x, a0.y, a0.z, a0.w, a1.x, a1.y, a1.z, a1.w};
            float bv[8] = {b0.x, b0.y, b0.z, b0.w, b1.x, b1.y, b1.z, b1.w};
            #pragma unroll
            for (int i = 0; i < 8; i++)
                #pragma unroll
                for (int j = 0; j < 8; j++)
                    acc[i][j] = fmaf(av[i], bv[j], acc[i][j]);
        }
    }

    // mode-2 epilogue
    #pragma unroll
    for (int ri = 0; ri < 2; ri++) {
        #pragma unroll
        for (int i = 0; i < 4; i++) {
            int row = rowBase + ri * 64 + tm4 + i;
            if (row >= M) continue;
            #pragma unroll
            for (int cj = 0; cj < 2; cj++) {
                int gcol = colBase + cj * 64 + tn4;
                float4 v = make_float4(acc[ri * 4 + i][cj * 4 + 0],
                                       acc[ri * 4 + i][cj * 4 + 1],
                                       acc[ri * 4 + i][cj * 4 + 2],
                                       acc[ri * 4 + i][cj * 4 + 3]);
                int r = gcol >> 4, f = gcol & 15;
                if (r < 6) {
                    *reinterpret_cast<float4*>(g_xt2 + ((size_t)r * NN + row) * 16 + f) = v;
                } else if (r == 6) {
                    float4 bv = *reinterpret_cast<const float4*>(bias + f);
                    v.x += bv.x; v.y += bv.y; v.z += bv.z; v.w += bv.w;
                    *reinterpret_cast<float4*>(g_z + (size_t)row * 16 + f) = v;
                }
            }
        }
    }
}

// ---------------- fused-root fp32 GEMM: 256x64 tiles ----------------
__global__ __launch_bounds__(256) void gemmRoot_k(
    const float* __restrict__ A, const float* __restrict__ Wf,
    const float* __restrict__ bias, int M, int K, int rowOff)
{
    __shared__ __align__(16) float As[2][16][264];
    __shared__ __align__(16) float Bs[2][16][64];
    const int tid = threadIdx.x;
    const int ty = tid >> 3;
    const int tx = tid & 7;
    const int rowBase = blockIdx.y * 256;

    const int bk = tid >> 4;
    const int bc = (tid & 15) << 2;

    float acc[8][8];
    #pragma unroll
    for (int i = 0; i < 8; i++)
        #pragma unroll
        for (int j = 0; j < 8; j++) acc[i][j] = 0.f;

    float4 pa[4];
    float4 pb;

    {
        int r = rowBase + tid;
        #pragma unroll
        for (int q = 0; q < 4; q++)
            pa[q] = (r < M) ? *reinterpret_cast<const float4*>(A + (size_t)r * K + q * 4)
                            : make_float4(0.f, 0.f, 0.f, 0.f);
        pb = *reinterpret_cast<const float4*>(Wf + (size_t)bk * 64 + bc);
    }
    {
        #pragma unroll
        for (int q = 0; q < 4; q++) {
            As[0][q * 4 + 0][tid] = pa[q].x;
            As[0][q * 4 + 1][tid] = pa[q].y;
            As[0][q * 4 + 2][tid] = pa[q].z;
            As[0][q * 4 + 3][tid] = pa[q].w;
        }
        *reinterpret_cast<float4*>(&Bs[0][bk][bc]) = pb;
    }
    __syncthreads();

    const int nk = K >> 4;
    for (int ch = 1; ch < nk; ch++) {
        int k0 = ch << 4;
        {
            int r = rowBase + tid;
            #pragma unroll
            for (int q = 0; q < 4; q++)
                pa[q] = (r < M) ? *reinterpret_cast<const float4*>(A + (size_t)r * K + k0 + q * 4)
                                : make_float4(0.f, 0.f, 0.f, 0.f);
            pb = *reinterpret_cast<const float4*>(Wf + (size_t)(k0 + bk) * 64 + bc);
        }
        int pbuf = (ch - 1) & 1;
        #pragma unroll
        for (int kk = 0; kk < 16; kk++) {
            float4 a0 = *reinterpret_cast<const float4*>(&As[pbuf][kk][ty << 2]);
            float4 a1 = *reinterpret_cast<const float4*>(&As[pbuf][kk][128 + (ty << 2)]);
            float4 b0 = *reinterpret_cast<const float4*>(&Bs[pbuf][kk][tx << 2]);
            float4 b1 = *reinterpret_cast<const float4*>(&Bs[pbuf][kk][32 + (tx << 2)]);
            float av[8] = {a0.x, a0.y, a0.z, a0.w, a1.x, a1.y, a1.z, a1.w};
            float bv[8] = {b0.x, b0.y, b0.z, b0.w, b1.x, b1.y, b1.z, b1.w};
            #pragma unroll
            for (int i = 0; i < 8; i++)
                #pragma unroll
                for (int j = 0; j < 8; j++)
                    acc[i][j] = fmaf(av[i], bv[j], acc[i][j]);
        }
        int buf = ch & 1;
        #pragma unroll
        for (int q = 0; q < 4; q++) {
            As[buf][q * 4 + 0][tid] = pa[q].x;
            As[buf][q * 4 + 1][tid] = pa[q].y;
            As[buf][q * 4 + 2][tid] = pa[q].z;
            As[buf][q * 4 + 3][tid] = pa[q].w;
        }
        *reinterpret_cast<float4*>(&Bs[buf][bk][bc]) = pb;
        __syncthreads();
    }
    {
        int pbuf = (nk - 1) & 1;
        #pragma unroll
        for (int kk = 0; kk < 16; kk++) {
            float4 a0 = *reinterpret_cast<const float4*>(&As[pbuf][kk][ty << 2]);
            float4 a1 = *reinterpret_cast<const float4*>(&As[pbuf][kk][128 + (ty << 2)]);
            float4 b0 = *reinterpret_cast<const float4*>(&Bs[pbuf][kk][tx << 2]);
            float4 b1 = *reinterpret_cast<const float4*>(&Bs[pbuf][kk][32 + (tx << 2)]);
            float av[8] = {a0.x, a0.y, a0.z, a0.w, a1.x, a1.y, a1.z, a1.w};
            float bv[8] = {b0.x, b0.y, b0.z, b0.w, b1.x, b1.y, b1.z, b1.w};
            #pragma unroll
            for (int i = 0; i < 8; i++)
                #pragma unroll
                for (int j = 0; j < 8; j++)
                    acc[i][j] = fmaf(av[i], bv[j], acc[i][j]);
        }
    }

    #pragma unroll
    for (int ri = 0; ri < 2; ri++) {
        #pragma unroll
        for (int i = 0; i < 4; i++) {
            int row = rowBase + ri * 128 + (ty << 2) + i;
            if (row >= M) continue;
            #pragma unroll
            for (int cj = 0; cj < 2; cj++) {
                int c = cj * 32 + (tx << 2);
                float4 bv = *reinterpret_cast<const float4*>(bias + c);
                float4 v = make_float4(acc[ri * 4 + i][cj * 4 + 0] + bv.x,
                                       acc[ri * 4 + i][cj * 4 + 1] + bv.y,
                                       acc[ri * 4 + i][cj * 4 + 2] + bv.z,
                                       acc[ri * 4 + i][cj * 4 + 3] + bv.w);
                *reinterpret_cast<float4*>(g_y + (size_t)(row + rowOff) * 64 + c) = v;
            }
        }
    }
}

// ---------------- fp16 tensor-core GEMM core ----------------
__device__ __forceinline__ void mma16816(float* c, const uint32_t* a, uint32_t b0, uint32_t b1) {
    asm volatile("mma.sync.aligned.m16n8k16.row.col.f32.f16.f16.f32 "
                 "{%0,%1,%2,%3}, {%4,%5,%6,%7}, {%8,%9}, {%0,%1,%2,%3};\n"
                 : "+f"(c[0]), "+f"(c[1]), "+f"(c[2]), "+f"(c[3])
                 : "r"(a[0]), "r"(a[1]), "r"(a[2]), "r"(a[3]), "r"(b0), "r"(b1));
}

// cp.async double-buffered mainloop body shared by both hgemm kernels.
// Panels: As/Bs [2][128][40] halves (pad 40 -> 20 words/row, conflict-free fragments).
// Per 32-k chunk: two s-steps of k16.

// layer-1 relation transforms: xt_h[r][row][o] = sum_k x_h[row][k] * W1ct_h[r*64+o][k]
__global__ __launch_bounds__(256) void hgemm_xt_k() {
    __shared__ __align__(16) __half As[2][128][40];
    __shared__ __align__(16) __half Bs[2][128][40];
    const int tid = threadIdx.x;
    const int lane = tid & 31;
    const int warp = tid >> 5;
    const int wm = warp >> 1;
    const int wn = warp & 1;
    const int rowBase = blockIdx.y * 128;
    const int colBase = blockIdx.x * 128;

    float acc[2][8][4];
    #pragma unroll
    for (int mt = 0; mt < 2; mt++)
        #pragma unroll
        for (int nt = 0; nt < 8; nt++)
            acc[mt][nt][0] = acc[mt][nt][1] = acc[mt][nt][2] = acc[mt][nt][3] = 0.f;

    const int ldrow = tid >> 1;         // 0..127
    const int ldseg = tid & 1;          // 0/1 -> 16-half segment pair
    const int grow = rowBase + ldrow;
    const int aIn = (grow < NN) ? 16 : 0;
    const __half* aSrc = g_x_h + (size_t)(grow < NN ? grow : 0) * 128 + ldseg * 16;
    const __half* bSrc = g_W1ct_h + (size_t)(colBase + ldrow) * 128 + ldseg * 16;

    uint32_t aDst0 = (uint32_t)__cvta_generic_to_shared(&As[0][ldrow][ldseg * 16]);
    uint32_t aDst1 = (uint32_t)__cvta_generic_to_shared(&As[1][ldrow][ldseg * 16]);
    uint32_t bDst0 = (uint32_t)__cvta_generic_to_shared(&Bs[0][ldrow][ldseg * 16]);
    uint32_t bDst1 = (uint32_t)__cvta_generic_to_shared(&Bs[1][ldrow][ldseg * 16]);

    const int NCH = 4;   // K=128 / 32
    cpasync16(aDst0,      aSrc, aIn);
    cpasync16(aDst0 + 16, aSrc + 8, aIn);
    cpasync16(bDst0,      bSrc, 16);
    cpasync16(bDst0 + 16, bSrc + 8, 16);
    cpasync_commit();

    for (int ch = 0; ch < NCH; ch++) {
        if (ch + 1 < NCH) {
            int koff = (ch + 1) * 32;
            uint32_t ad = ((ch + 1) & 1) ? aDst1 : aDst0;
            uint32_t bd = ((ch + 1) & 1) ? bDst1 : bDst0;
            cpasync16(ad,      aSrc + koff, aIn);
            cpasync16(ad + 16, aSrc + koff + 8, aIn);
            cpasync16(bd,      bSrc + koff, 16);
            cpasync16(bd + 16, bSrc + koff + 8, 16);
            cpasync_commit();
            cpasync_wait1();
        } else {
            cpasync_wait0();
        }
        __syncthreads();

        const int buf = ch & 1;
        const int g = lane >> 2, t = lane & 3;
        #pragma unroll
        for (int s = 0; s < 2; s++) {
            const int k0 = s * 16 + 2 * t;
            uint32_t a[2][4];
            #pragma unroll
            for (int mt = 0; mt < 2; mt++) {
                int rb = wm * 32 + mt * 16;
                a[mt][0] = *reinterpret_cast<const uint32_t*>(&As[buf][rb + g][k0]);
                a[mt][1] = *reinterpret_cast<const uint32_t*>(&As[buf][rb + g + 8][k0]);
                a[mt][2] = *reinterpret_cast<const uint32_t*>(&As[buf][rb + g][k0 + 8]);
                a[mt][3] = *reinterpret_cast<const uint32_t*>(&As[buf][rb + g + 8][k0 + 8]);
            }
            uint32_t b[8][2];
            #pragma unroll
            for (int nt = 0; nt < 8; nt++) {
                int nb = wn * 64 + nt * 8;
                b[nt][0] = *reinterpret_cast<const uint32_t*>(&Bs[buf][nb + g][k0]);
                b[nt][1] = *reinterpret_cast<const uint32_t*>(&Bs[buf][nb + g][k0 + 8]);
            }
            #pragma unroll
            for (int mt = 0; mt < 2; mt++)
                #pragma unroll
                for (int nt = 0; nt < 8; nt++)
                    mma16816(acc[mt][nt], a[mt], b[nt][0], b[nt][1]);
        }
        __syncthreads();
    }

    const int gid = lane >> 2, tig = lane & 3;
    #pragma unroll
    for (int mt = 0; mt < 2; mt++) {
        int grow0 = rowBase + wm * 32 + mt * 16 + gid;
        #pragma unroll
        for (int nt = 0; nt < 8; nt++) {
            int gn = colBase + wn * 64 + nt * 8 + tig * 2;
            int r = gn >> 6, f = gn & 63;
            if (grow0 < NN) {
                __half2 h = __floats2half2_rn(acc[mt][nt][0], acc[mt][nt][1]);
                *reinterpret_cast<__half2*>(g_xt_h + ((size_t)r * NN + grow0) * 64 + f) = h;
            }
            if (grow0 + 8 < NN) {
                __half2 h = __floats2half2_rn(acc[mt][nt][2], acc[mt][nt][3]);
                *reinterpret_cast<__half2*>(g_xt_h + ((size_t)r * NN + grow0 + 8) * 64 + f) = h;
            }
        }
    }
}

// fp16 projection: x_h[(row+rowOff)][0..127] = in_h[row][K] @ w_hᵀ + bias
__global__ __launch_bounds__(256) void hgemm_proj_k(int M, int K, int inOff, int wOff,
                                                    const float* __restrict__ bias, int rowOff) {
    __shared__ __align__(16) __half As[2][128][40];
    __shared__ __align__(16) __half Bs[2][128][40];
    const int tid = threadIdx.x;
    const int lane = tid & 31;
    const int warp = tid >> 5;
    const int wm = warp >> 1;
    const int wn = warp & 1;
    const int rowBase = blockIdx.y * 128;

    float acc[2][8][4];
    #pragma unroll
    for (int mt = 0; mt < 2; mt++)
        #pragma unroll
        for (int nt = 0; nt < 8; nt++)
            acc[mt][nt][0] = acc[mt][nt][1] = acc[mt][nt][2] = acc[mt][nt][3] = 0.f;

    const int ldrow = tid >> 1;
    const int ldseg = tid & 1;
    const int grow = rowBase + ldrow;
    const int aIn = (grow < M) ? 16 : 0;
    const __half* aSrc = g_in_h + inOff + (size_t)(grow < M ? grow : 0) * K + ldseg * 16;
    const __half* bSrc = g_w_h + wOff + (size_t)ldrow * K + ldseg * 16;

    uint32_t aDst0 = (uint32_t)__cvta_generic_to_shared(&As[0][ldrow][ldseg * 16]);
    uint32_t aDst1 = (uint32_t)__cvta_generic_to_shared(&As[1][ldrow][ldseg * 16]);
    uint32_t bDst0 = (uint32_t)__cvta_generic_to_shared(&Bs[0][ldrow][ldseg * 16]);
    uint32_t bDst1 = (uint32_t)__cvta_generic_to_shared(&Bs[1][ldrow][ldseg * 16]);

    const int NCH = K >> 5;
    cpasync16(aDst0,      aSrc, aIn);
    cpasync16(aDst0 + 16, aSrc + 8, aIn);
    cpasync16(bDst0,      bSrc, 16);
    cpasync16(bDst0 + 16, bSrc + 8, 16);
    cpasync_commit();

    for (int ch = 0; ch < NCH; ch++) {
        if (ch + 1 < NCH) {
            int koff = (ch + 1) * 32;
            uint32_t ad = ((ch + 1) & 1) ? aDst1 : aDst0;
            uint32_t bd = ((ch + 1) & 1) ? bDst1 : bDst0;
            cpasync16(ad,      aSrc + koff, aIn);
            cpasync16(ad + 16, aSrc + koff + 8, aIn);
            cpasync16(bd,      bSrc + koff, 16);
            cpasync16(bd + 16, bSrc + koff + 8, 16);
            cpasync_commit();
            cpasync_wait1();
        } else {
            cpasync_wait0();
        }
        __syncthreads();

        const int buf = ch & 1;
        const int g = lane >> 2, t = lane & 3;
        #pragma unroll
        for (int s = 0; s < 2; s++) {
            const int k0 = s * 16 + 2 * t;
            uint32_t a[2][4];
            #pragma unroll
            for (int mt = 0; mt < 2; mt++) {
                int rb = wm * 32 + mt * 16;
                a[mt][0] = *reinterpret_cast<const uint32_t*>(&As[buf][rb + g][k0]);
                a[mt][1] = *reinterpret_cast<const uint32_t*>(&As[buf][rb + g + 8][k0]);
                a[mt][2] = *reinterpret_cast<const uint32_t*>(&As[buf][rb + g][k0 + 8]);
                a[mt][3] = *reinterpret_cast<const uint32_t*>(&As[buf][rb + g + 8][k0 + 8]);
            }
            uint32_t b[8][2];
            #pragma unroll
            for (int nt = 0; nt < 8; nt++) {
                int nb = wn * 64 + nt * 8;
                b[nt][0] = *reinterpret_cast<const uint32_t*>(&Bs[buf][nb + g][k0]);
                b[nt][1] = *reinterpret_cast<const uint32_t*>(&Bs[buf][nb + g][k0 + 8]);
            }
            #pragma unroll
            for (int mt = 0; mt < 2; mt++)
                #pragma unroll
                for (int nt = 0; nt < 8; nt++)
                    mma16816(acc[mt][nt], a[mt], b[nt][0], b[nt][1]);
        }
        __syncthreads();
    }

    const int gid = lane >> 2, tig = lane & 3;
    #pragma unroll
    for (int mt = 0; mt < 2; mt++) {
        int lrow0 = rowBase + wm * 32 + mt * 16 + gid;
        #pragma unroll
        for (int nt = 0; nt < 8; nt++) {
            int gn = wn * 64 + nt * 8 + tig * 2;
            float b0 = bias[gn], b1 = bias[gn + 1];
            if (lrow0 < M) {
                __half2 h = __floats2half2_rn(acc[mt][nt][0] + b0, acc[mt][nt][1] + b1);
                *reinterpret_cast<__half2*>(
                    g_x_h + (size_t)(lrow0 + rowOff) * 128 + gn) = h;
            }
            if (lrow0 + 8 < M) {
                __half2 h = __floats2half2_rn(acc[mt][nt][2] + b0, acc[mt][nt][3] + b1);
                *reinterpret_cast<__half2*>(
                    g_x_h + (size_t)(lrow0 + 8 + rowOff) * 128 + gn) = h;
            }
        }
    }
}

// ---------------- edge aggregation (CSR by dst, no float atomics) ----------------
__device__ __forceinline__ float sel_inv(int t, float i0, float i1, float i2,
                                         float i3, float i4, float i5) {
    float w = i5;
    w = (t == 4) ? i4 : w;
    w = (t == 3) ? i3 : w;
    w = (t == 2) ? i2 : w;
    w = (t == 1) ? i1 : w;
    w = (t == 0) ? i0 : w;
    return w;
}

// layer 1: F=64 fp16, one warp per dst
__global__ __launch_bounds__(256) void agg1_k() {
    int gw = (blockIdx.x * blockDim.x + threadIdx.x) >> 5;
    int lane = threadIdx.x & 31;
    if (gw >= NN) return;
    const int dst = gw;
    const int beg = g_rowptr[dst];
    const int end = g_rowptr[dst + 1];
    const float i0 = g_inv[dst],          i1 = g_inv[NN + dst],     i2 = g_inv[2 * NN + dst],
                i3 = g_inv[3 * NN + dst], i4 = g_inv[4 * NN + dst], i5 = g_inv[5 * NN + dst];
    const __half2* __restrict__ base = reinterpret_cast<const __half2*>(g_xt_h);
    float ax = 0.f, ay = 0.f;
    int e = beg;
    for (; e + 8 <= end; e += 8) {
        #pragma unroll
        for (int u = 0; u < 8; u++) {
            int p = g_eidx[e + u];
            __half2 h = base[(size_t)((p >> 17) * NN + (p & 131071)) * 32 + lane];
            float2 v = __half22float2(h);
            float w = sel_inv(p >> 17, i0, i1, i2, i3, i4, i5);
            ax = fmaf(w, v.x, ax); ay = fmaf(w, v.y, ay);
        }
    }
    for (; e < end; e++) {
        int p = g_eidx[e];
        __half2 h = base[(size_t)((p >> 17) * NN + (p & 131071)) * 32 + lane];
        float2 v = __half22float2(h);
        float w = sel_inv(p >> 17, i0, i1, i2, i3, i4, i5);
        ax = fmaf(w, v.x, ax); ay = fmaf(w, v.y, ay);
    }
    float2* yrow = reinterpret_cast<float2*>(g_y) + (size_t)dst * 32 + lane;
    float2 cur = *yrow;
    cur.x += ax; cur.y += ay;
    *yrow = cur;
}

// layer 2: F=16 fp32, 16-thread group per dst
__global__ __launch_bounds__(256) void agg2_k() {
    int g = (blockIdx.x * blockDim.x + threadIdx.x) >> 4;
    int lane = threadIdx.x & 15;
    if (g >= NN) return;
    const int dst = g;
    const int beg = g_rowptr[dst];
    const int end = g_rowptr[dst + 1];
    const float i0 = g_inv[dst],          i1 = g_inv[NN + dst],     i2 = g_inv[2 * NN + dst],
                i3 = g_inv[3 * NN + dst], i4 = g_inv[4 * NN + dst], i5 = g_inv[5 * NN + dst];
    float acc = 0.f;
    int e = beg;
    for (; e + 4 <= end; e += 4) {
        int p0 = g_eidx[e], p1 = g_eidx[e + 1], p2 = g_eidx[e + 2], p3 = g_eidx[e + 3];
        float v0 = g_xt2[(size_t)((p0 >> 17) * NN + (p0 & 131071)) * 16 + lane];
        float v1 = g_xt2[(size_t)((p1 >> 17) * NN + (p1 & 131071)) * 16 + lane];
        float v2 = g_xt2[(size_t)((p2 >> 17) * NN + (p2 & 131071)) * 16 + lane];
        float v3 = g_xt2[(size_t)((p3 >> 17) * NN + (p3 & 131071)) * 16 + lane];
        acc = fmaf(sel_inv(p0 >> 17, i0, i1, i2, i3, i4, i5), v0, acc);
        acc = fmaf(sel_inv(p1 >> 17, i0, i1, i2, i3, i4, i5), v1, acc);
        acc = fmaf(sel_inv(p2 >> 17, i0, i1, i2, i3, i4, i5), v2, acc);
        acc = fmaf(sel_inv(p3 >> 17, i0, i1, i2, i3, i4, i5), v3, acc);
    }
    for (; e < end; e++) {
        int p = g_eidx[e];
        float v = g_xt2[(size_t)((p >> 17) * NN + (p & 131071)) * 16 + lane];
        acc = fmaf(sel_inv(p >> 17, i0, i1, i2, i3, i4, i5), v, acc);
    }
    g_z[(size_t)dst * 16 + lane] += acc;
}

// ---------------- softmax over first 30000 rows ----------------
__global__ __launch_bounds__(256) void softmax_k(float* __restrict__ out) {
    int r = blockIdx.x * blockDim.x + threadIdx.x;
    if (r >= 30000) return;
    const float4* zr = reinterpret_cast<const float4*>(g_z + (size_t)r * 16);
    float vals[16];
    *reinterpret_cast<float4*>(&vals[0])  = zr[0];
    *reinterpret_cast<float4*>(&vals[4])  = zr[1];
    *reinterpret_cast<float4*>(&vals[8])  = zr[2];
    *reinterpret_cast<float4*>(&vals[12]) = zr[3];
    float m = vals[0];
    #pragma unroll
    for (int i = 1; i < 16; i++) m = fmaxf(m, vals[i]);
    float s = 0.f;
    #pragma unroll
    for (int i = 0; i < 16; i++) { vals[i] = __expf(vals[i] - m); s += vals[i]; }
    float inv = 1.f / s;
    float4* o = reinterpret_cast<float4*>(out + (size_t)r * 16);
    o[0] = make_float4(vals[0] * inv,  vals[1] * inv,  vals[2] * inv,  vals[3] * inv);
    o[1] = make_float4(vals[4] * inv,  vals[5] * inv,  vals[6] * inv,  vals[7] * inv);
    o[2] = make_float4(vals[8] * inv,  vals[9] * inv,  vals[10] * inv, vals[11] * inv);
    o[3] = make_float4(vals[12] * inv, vals[13] * inv, vals[14] * inv, vals[15] * inv);
}

// ---------------- launcher ----------------
extern "C" void kernel_launch(void* const* d_in, const int* in_sizes, int n_in,
                              void* d_out, int out_size) {
    const float* x0     = (const float*)d_in[0];
    const float* x1     = (const float*)d_in[1];
    const float* x2     = (const float*)d_in[2];
    const float* lw0    = (const float*)d_in[3];
    const float* lb0    = (const float*)d_in[4];
    const float* lw1    = (const float*)d_in[5];
    const float* lb1    = (const float*)d_in[6];
    const float* lw2    = (const float*)d_in[7];
    const float* lb2    = (const float*)d_in[8];
    const float* bases1 = (const float*)d_in[9];
    const float* comp1  = (const float*)d_in[10];
    const float* root1  = (const float*)d_in[11];
    const float* bias1  = (const float*)d_in[12];
    const float* bases2 = (const float*)d_in[13];
    const float* comp2  = (const float*)d_in[14];
    const float* root2  = (const float*)d_in[15];
    const float* bias2  = (const float*)d_in[16];
    const int*   eidx   = (const int*)d_in[17];
    const int*   etyp   = (const int*)d_in[18];

    float *py, *pWf, *pbf, *pW2c;
    cudaGetSymbolAddress((void**)&py,   g_y);
    cudaGetSymbolAddress((void**)&pWf,  g_Wf);
    cudaGetSymbolAddress((void**)&pbf,  g_bf);
    cudaGetSymbolAddress((void**)&pW2c, g_W2c);

    const int CONV4 = (M0 * K0 + M1 * K1 + M2 * K2) / 4;
    const int PREPW = 128 * (K0 + K1 + K2) + (K0 + K1 + K2) * 64 + 192;

    convIn_k<<<(CONV4 + 255) / 256, 256>>>(x0, x1, x2);                                     // 0
    prepW_k<<<(PREPW + 255) / 256, 256>>>(lw0, lw1, lw2, lb0, lb1, lb2, root1, bias1);      // 1
    zero_k<<<(6 * NN + 255) / 256, 256>>>();                                                // 2
    hgemm_proj_k<<<dim3(1, (M1 + 127) / 128), 256>>>(M1, K1, IN1_OFF, W1_OFF, lb1, M0);     // 3 (profiled)
    compWc_k<<<(128 * 384 + 64 * 128 + 255) / 256, 256>>>(comp1, bases1, comp2, bases2, root2); // 4
    count_k<<<(NE + 255) / 256, 256>>>(eidx, etyp);                                         // 5
    prep_k<<<(6 * NN + 255) / 256, 256>>>();                                                // 6
    scanA_k<<<NBLK, 256>>>();                                                               // 7
    scanB_k<<<1, 512>>>();                                                                  // 8
    scanC_k<<<NBLK, 256>>>();                                                               // 9
    fill_k<<<(NE + 255) / 256, 256>>>(eidx, etyp);                                          // 10
    hgemm_proj_k<<<dim3(1, (M0 + 127) / 128), 256>>>(M0, K0, IN0_OFF, W0_OFF, lb0, 0);      // 11
    hgemm_proj_k<<<dim3(1, (M2 + 127) / 128), 256>>>(M2, K2, IN2_OFF, W2_OFF, lb2, M0 + M1);// 12

    // layer-1 relation transforms (tensor cores)
    hgemm_xt_k<<<dim3(3, (NN + 127) / 128), 256>>>();                                       // 13

    // fused root path (exact fp32, from original inputs)
    gemmRoot_k<<<dim3(1, (M0 + 255) / 256), 256>>>(x0, pWf + WFR0 * 64, pbf,       M0, K0, 0);       // 14
    gemmRoot_k<<<dim3(1, (M1 + 255) / 256), 256>>>(x1, pWf + WFR1 * 64, pbf + 64,  M1, K1, M0);      // 15
    gemmRoot_k<<<dim3(1, (M2 + 255) / 256), 256>>>(x2, pWf + WFR2 * 64, pbf + 128, M2, K2, M0 + M1); // 16

    agg1_k<<<NN / 8, 256>>>();                                                              // 17

    // layer-2 fused fp32
    gemm128_k<<<dim3(1, (NN + 127) / 128), 256>>>(py, pW2c, bias2, NN, 64, 128);            // 18

    agg2_k<<<NN / 16, 256>>>();                                                             // 19

    softmax_k<<<(30000 + 255) / 256, 256>>>((float*)d_out);                                 // 20
}